// round 2
// baseline (speedup 1.0000x reference)
#include <cuda_runtime.h>
#include <math.h>

#define SQ    2048      // sequence length
#define DIM   2048
#define HEADS 16
#define KV    4
#define GG    4         // heads per kv head
#define DH    128
#define NW    255       // num compression windows
#define NKEYS 256       // NMEM + NW
#define NF    128       // num selection blocks
#define NSEL  4
#define SBS   16
#define SWIN  64
#define SCALE 0.08838834764831845f   // 1/sqrt(128)

// ---------------- scratch (device globals; no allocations allowed) -------------
__device__ float g_h[SQ*DIM];
__device__ float g_qkv[SQ*3072];
__device__ float g_comb[SQ*48];
__device__ float g_kwflat[KV*NW*2048];
__device__ float g_vwflat[KV*NW*2048];
__device__ float g_hidden[KV*NW*2048];
__device__ float g_craw[KV*NW*DH];
__device__ float g_ck[KV*NKEYS*DH];
__device__ float g_cv[KV*NKEYS*DH];
__device__ float g_rq[SQ*HEADS*DH];
__device__ float g_rk[KV*SQ*DH];
__device__ int   g_sel[KV*SQ*NSEL];
__device__ float g_att[SQ*HEADS*DH];

// ---------------- helpers ----------------
__device__ __forceinline__ float blkmax(float v, float* red, int t) {
    red[t] = v; __syncthreads();
    #pragma unroll
    for (int st = 128; st > 0; st >>= 1) {
        if (t < st) red[t] = fmaxf(red[t], red[t + st]);
        __syncthreads();
    }
    float r = red[0]; __syncthreads();
    return r;
}
__device__ __forceinline__ float blksum(float v, float* red, int t) {
    red[t] = v; __syncthreads();
    #pragma unroll
    for (int st = 128; st > 0; st >>= 1) {
        if (t < st) red[t] += red[t + st];
        __syncthreads();
    }
    float r = red[0]; __syncthreads();
    return r;
}

// ---------------- RMSNorm ----------------
__global__ void rmsnorm_kernel(const float* __restrict__ x, const float* __restrict__ g) {
    int s = blockIdx.x;
    int t = threadIdx.x;
    __shared__ float red[256];
    float acc = 0.f;
    for (int i = t; i < DIM; i += 256) { float v = x[s*DIM + i]; acc += v*v; }
    red[t] = acc; __syncthreads();
    for (int st = 128; st > 0; st >>= 1) {
        if (t < st) red[t] += red[t + st];
        __syncthreads();
    }
    float r = rsqrtf(red[0] / (float)DIM + 1e-6f);
    for (int i = t; i < DIM; i += 256) g_h[s*DIM + i] = x[s*DIM + i] * r * g[i];
}

// ---------------- generic tiled SGEMM, row-major A(M,K) x B(K,N) -> C(M,N) -----
// epi: 0 = none, 1 = +bias, 2 = +bias,relu, 3 = +bias,sigmoid
__global__ void sgemm(const float* __restrict__ A, const float* __restrict__ B,
                      const float* __restrict__ bias, float* __restrict__ C,
                      int M, int N, int K, int epi)
{
    __shared__ float As[16][64];
    __shared__ float Bs[16][64];
    int tid = threadIdx.x;
    int row0 = blockIdx.y * 64, col0 = blockIdx.x * 64;
    int tr = tid >> 4, tc = tid & 15;
    float acc[4][4] = {};
    for (int k0 = 0; k0 < K; k0 += 16) {
        #pragma unroll
        for (int i = 0; i < 4; i++) {
            int idx = tid + i * 256;           // 0..1023
            int r = idx >> 4, c = idx & 15;    // A tile 64x16
            int gr = row0 + r;
            As[c][r] = (gr < M) ? A[gr * K + k0 + c] : 0.f;
            int br = idx >> 6, bc = idx & 63;  // B tile 16x64
            int gc = col0 + bc;
            Bs[br][bc] = (gc < N) ? B[(k0 + br) * N + gc] : 0.f;
        }
        __syncthreads();
        #pragma unroll
        for (int kk = 0; kk < 16; kk++) {
            float a[4], b[4];
            #pragma unroll
            for (int u = 0; u < 4; u++) { a[u] = As[kk][tr*4 + u]; b[u] = Bs[kk][tc*4 + u]; }
            #pragma unroll
            for (int i = 0; i < 4; i++)
                #pragma unroll
                for (int j = 0; j < 4; j++)
                    acc[i][j] = fmaf(a[i], b[j], acc[i][j]);
        }
        __syncthreads();
    }
    #pragma unroll
    for (int i = 0; i < 4; i++) {
        int r = row0 + tr*4 + i;
        if (r >= M) continue;
        #pragma unroll
        for (int j = 0; j < 4; j++) {
            int c = col0 + tc*4 + j;
            if (c >= N) continue;
            float v = acc[i][j];
            if (epi >= 1) {
                v += bias[c];
                if (epi == 2) v = fmaxf(v, 0.f);
                else if (epi == 3) v = 1.f / (1.f + expf(-v));
            }
            C[r * N + c] = v;
        }
    }
}

// ---------------- window gather + positional add ----------------
__global__ void build_win(const float* __restrict__ k_pos, const float* __restrict__ v_pos) {
    int w = blockIdx.x, kh = blockIdx.y;
    int row = kh * NW + w;
    for (int i = threadIdx.x; i < 2048; i += 256) {
        int c = i >> 7, d = i & 127;
        int s = w * 8 + c;
        g_kwflat[row*2048 + i] = g_qkv[s*3072 + 2048 + kh*DH + d] + k_pos[kh*2048 + i];
        g_vwflat[row*2048 + i] = g_qkv[s*3072 + 2560 + kh*DH + d] + v_pos[kh*2048 + i];
    }
}

// ---------------- assemble ck / cv (prepend memory token) ----------------
__global__ void assemble_c(const float* __restrict__ mem_kv, int which) {
    int j = blockIdx.x, kh = blockIdx.y;
    int d = threadIdx.x; // 128
    float v;
    if (j == 0) v = mem_kv[which * (KV*DH) + kh*DH + d];
    else        v = g_craw[(kh*NW + (j-1))*DH + d];
    float* dst = which ? g_cv : g_ck;
    dst[(kh*NKEYS + j)*DH + d] = v;
}

// ---------------- RoPE for q (16 heads) and k (4 heads) ----------------
__global__ void rope_kernel() {
    int s = blockIdx.x;
    for (int p = threadIdx.x; p < 20 * 64; p += 256) {
        int head = p >> 6;
        int i = p & 63;
        float invf = 1.0f / powf(10000.0f, (float)i * (1.0f / 64.0f));
        float ang = (float)s * invf;
        float sn, cs;
        sincosf(ang, &sn, &cs);
        if (head < HEADS) {
            const float* src = &g_qkv[s*3072 + head*DH];
            float t1 = src[2*i], t2 = src[2*i + 1];
            float* dst = &g_rq[(s*HEADS + head)*DH];
            dst[2*i]     = t1*cs - t2*sn;
            dst[2*i + 1] = t1*sn + t2*cs;
        } else {
            int kh = head - HEADS;
            const float* src = &g_qkv[s*3072 + 2048 + kh*DH];
            float t1 = src[2*i], t2 = src[2*i + 1];
            float* dst = &g_rk[(kh*SQ + s)*DH];
            dst[2*i]     = t1*cs - t2*sn;
            dst[2*i + 1] = t1*sn + t2*cs;
        }
    }
}

// ---------------- compressed attention + importance + top-k ----------------
// block = (q, kv): 4 G-heads handled together, 256 keys
__global__ void comp_attn() {
    int q = blockIdx.x, kv = blockIdx.y;
    int t = threadIdx.x;
    __shared__ __align__(16) float qs[4][DH];
    __shared__ float sim[4][NKEYS];
    __shared__ float red[256];
    __shared__ float impsh[NF];

    for (int i = t; i < 4*DH; i += 256) {
        int g = i >> 7, d = i & 127;
        qs[g][d] = g_qkv[q*3072 + (kv*GG + g)*DH + d];
    }
    __syncthreads();

    {   // similarity: thread t handles key j=t for all 4 heads
        int j = t;
        const float4* kr = reinterpret_cast<const float4*>(&g_ck[(kv*NKEYS + j)*DH]);
        const float4* q0 = reinterpret_cast<const float4*>(qs[0]);
        const float4* q1 = reinterpret_cast<const float4*>(qs[1]);
        const float4* q2 = reinterpret_cast<const float4*>(qs[2]);
        const float4* q3 = reinterpret_cast<const float4*>(qs[3]);
        float s0=0,s1=0,s2=0,s3=0;
        #pragma unroll 8
        for (int d4 = 0; d4 < 32; d4++) {
            float4 b = kr[d4]; float4 a;
            a = q0[d4]; s0 += a.x*b.x + a.y*b.y + a.z*b.z + a.w*b.w;
            a = q1[d4]; s1 += a.x*b.x + a.y*b.y + a.z*b.z + a.w*b.w;
            a = q2[d4]; s2 += a.x*b.x + a.y*b.y + a.z*b.z + a.w*b.w;
            a = q3[d4]; s3 += a.x*b.x + a.y*b.y + a.z*b.z + a.w*b.w;
        }
        bool valid = (j == 0) || (q > (j - 1) * 8 + 15);
        sim[0][j] = valid ? s0*SCALE : -INFINITY;
        sim[1][j] = valid ? s1*SCALE : -INFINITY;
        sim[2][j] = valid ? s2*SCALE : -INFINITY;
        sim[3][j] = valid ? s3*SCALE : -INFINITY;
    }
    __syncthreads();

    for (int g = 0; g < 4; g++) {
        float v = sim[g][t];
        float m = blkmax(v, red, t);
        float e = expf(v - m);           // exp(-inf)=0
        float s = blksum(e, red, t);
        sim[g][t] = e / s;
        __syncthreads();
    }

    // cout * gate0
    for (int p = t; p < 512; p += 256) {
        int g = p >> 7, d = p & 127;
        float acc = 0.f;
        const float* cvp = &g_cv[kv*NKEYS*DH + d];
        for (int j = 0; j < NKEYS; j++) acc += sim[g][j] * cvp[j*DH];
        int head = kv*GG + g;
        g_att[(q*HEADS + head)*DH + d] = g_comb[q*48 + head*3 + 0] * acc;
    }

    // importance per selection block
    if (t < NF) {
        int f = t;
        float a = 0.f;
        #pragma unroll
        for (int g = 0; g < 4; g++) {
            a += sim[g][1 + 2*f];
            if (2*f + 1 < NW) a += sim[g][2 + 2*f];
        }
        impsh[f] = (f < (q >> 4)) ? a * 0.125f : -1.0f;
    }
    __syncthreads();
    if (t == 0) {   // top-4, lowest-index tie-break (matches jax top_k)
        for (int it = 0; it < NSEL; it++) {
            float best = -1e30f; int bi = 0;
            for (int f = 0; f < NF; f++)
                if (impsh[f] > best) { best = impsh[f]; bi = f; }
            g_sel[(kv*SQ + q)*NSEL + it] = (best > 0.f) ? bi : -1;
            impsh[bi] = -1e30f;
        }
    }
}

// ---------------- selected + sliding window attention ----------------
__global__ void sel_sw_attn() {
    int q = blockIdx.x, kv = blockIdx.y;
    int t = threadIdx.x;
    __shared__ __align__(16) float qs[4][DH];
    __shared__ float fs[4][80];
    __shared__ float ws[4][65];
    __shared__ int   kp[80];
    __shared__ float red[256];

    for (int i = t; i < 4*DH; i += 256) {
        int g = i >> 7, d = i & 127;
        qs[g][d] = g_rq[(q*HEADS + kv*GG + g)*DH + d];
    }
    if (t < 80) {
        int pos, valid;
        if (t < 64) {
            int blk = g_sel[(kv*SQ + q)*NSEL + (t >> 4)];
            pos = blk*SBS + (t & 15);
            valid = (blk >= 0) && (pos <= q);
        } else {
            pos = (q & ~(SBS-1)) + (t - 64);
            valid = (pos <= q);
        }
        kp[t] = valid ? pos : -1;
    }
    __syncthreads();

    int kbase = (q >= SWIN) ? (q - SWIN) : 0;
    int cnt = q - kbase + 1;   // <= 65

    if (t < 80) {   // selected sims (all 4 heads per key)
        int pos = kp[t];
        float a0=-INFINITY,a1=-INFINITY,a2=-INFINITY,a3=-INFINITY;
        if (pos >= 0) {
            const float4* kr = reinterpret_cast<const float4*>(&g_rk[(kv*SQ + pos)*DH]);
            const float4* q0 = reinterpret_cast<const float4*>(qs[0]);
            const float4* q1 = reinterpret_cast<const float4*>(qs[1]);
            const float4* q2 = reinterpret_cast<const float4*>(qs[2]);
            const float4* q3 = reinterpret_cast<const float4*>(qs[3]);
            float s0=0,s1=0,s2=0,s3=0;
            #pragma unroll 8
            for (int d4 = 0; d4 < 32; d4++) {
                float4 b = kr[d4]; float4 a;
                a = q0[d4]; s0 += a.x*b.x + a.y*b.y + a.z*b.z + a.w*b.w;
                a = q1[d4]; s1 += a.x*b.x + a.y*b.y + a.z*b.z + a.w*b.w;
                a = q2[d4]; s2 += a.x*b.x + a.y*b.y + a.z*b.z + a.w*b.w;
                a = q3[d4]; s3 += a.x*b.x + a.y*b.y + a.z*b.z + a.w*b.w;
            }
            a0 = s0*SCALE; a1 = s1*SCALE; a2 = s2*SCALE; a3 = s3*SCALE;
        }
        fs[0][t]=a0; fs[1][t]=a1; fs[2][t]=a2; fs[3][t]=a3;
    }
    if (t >= 128 && t < 193) {  // sliding sims (run in parallel on other warps)
        int j = t - 128;        // 0..64
        float a0=-INFINITY,a1=-INFINITY,a2=-INFINITY,a3=-INFINITY;
        if (j < cnt) {
            int pos = kbase + j;
            const float4* kr = reinterpret_cast<const float4*>(&g_rk[(kv*SQ + pos)*DH]);
            const float4* q0 = reinterpret_cast<const float4*>(qs[0]);
            const float4* q1 = reinterpret_cast<const float4*>(qs[1]);
            const float4* q2 = reinterpret_cast<const float4*>(qs[2]);
            const float4* q3 = reinterpret_cast<const float4*>(qs[3]);
            float s0=0,s1=0,s2=0,s3=0;
            #pragma unroll 8
            for (int d4 = 0; d4 < 32; d4++) {
                float4 b = kr[d4]; float4 a;
                a = q0[d4]; s0 += a.x*b.x + a.y*b.y + a.z*b.z + a.w*b.w;
                a = q1[d4]; s1 += a.x*b.x + a.y*b.y + a.z*b.z + a.w*b.w;
                a = q2[d4]; s2 += a.x*b.x + a.y*b.y + a.z*b.z + a.w*b.w;
                a = q3[d4]; s3 += a.x*b.x + a.y*b.y + a.z*b.z + a.w*b.w;
            }
            a0 = s0*SCALE; a1 = s1*SCALE; a2 = s2*SCALE; a3 = s3*SCALE;
        }
        ws[0][j]=a0; ws[1][j]=a1; ws[2][j]=a2; ws[3][j]=a3;
    }
    __syncthreads();

    for (int g = 0; g < 4; g++) {
        float v = (t < 80) ? fs[g][t] : -INFINITY;
        float m = blkmax(v, red, t);
        float e = (t < 80) ? expf(v - m) : 0.f;
        float s = blksum(e, red, t);
        if (t < 80) fs[g][t] = e / s;
        float v2 = (t < 65) ? ws[g][t] : -INFINITY;
        float m2 = blkmax(v2, red, t);
        float e2 = (t < 65) ? expf(v2 - m2) : 0.f;
        float s2 = blksum(e2, red, t);
        if (t < 65) ws[g][t] = e2 / s2;
        __syncthreads();
    }

    for (int p = t; p < 512; p += 256) {
        int g = p >> 7, d = p & 127;
        float fa = 0.f;
        for (int j = 0; j < 80; j++) {
            int pos = kp[j];
            if (pos >= 0) fa += fs[g][j] * g_qkv[pos*3072 + 2560 + kv*DH + d];
        }
        float wa = 0.f;
        for (int j = 0; j < cnt; j++)
            wa += ws[g][j] * g_qkv[(kbase + j)*3072 + 2560 + kv*DH + d];
        int head = kv*GG + g;
        float g1 = g_comb[q*48 + head*3 + 1];
        float g2 = g_comb[q*48 + head*3 + 2];
        g_att[(q*HEADS + head)*DH + d] += g1*fa + g2*wa;
    }
}

// ---------------- launcher ----------------
extern "C" void kernel_launch(void* const* d_in, const int* in_sizes, int n_in,
                              void* d_out, int out_size) {
    const float* x      = (const float*)d_in[0];
    const float* gnorm  = (const float*)d_in[1];
    const float* w_qkv  = (const float*)d_in[2];
    const float* k_pos  = (const float*)d_in[3];
    const float* v_pos  = (const float*)d_in[4];
    const float* mem_kv = (const float*)d_in[5];
    const float* kc_w1  = (const float*)d_in[6];
    const float* kc_b1  = (const float*)d_in[7];
    const float* kc_w2  = (const float*)d_in[8];
    const float* kc_b2  = (const float*)d_in[9];
    const float* vc_w1  = (const float*)d_in[10];
    const float* vc_b1  = (const float*)d_in[11];
    const float* vc_w2  = (const float*)d_in[12];
    const float* vc_b2  = (const float*)d_in[13];
    const float* w_comb = (const float*)d_in[14];
    const float* b_comb = (const float*)d_in[15];
    const float* w_out  = (const float*)d_in[16];
    float* out = (float*)d_out;

    float *h, *qkv, *comb, *kwf, *vwf, *hid, *craw, *att;
    cudaGetSymbolAddress((void**)&h,    g_h);
    cudaGetSymbolAddress((void**)&qkv,  g_qkv);
    cudaGetSymbolAddress((void**)&comb, g_comb);
    cudaGetSymbolAddress((void**)&kwf,  g_kwflat);
    cudaGetSymbolAddress((void**)&vwf,  g_vwflat);
    cudaGetSymbolAddress((void**)&hid,  g_hidden);
    cudaGetSymbolAddress((void**)&craw, g_craw);
    cudaGetSymbolAddress((void**)&att,  g_att);

    rmsnorm_kernel<<<SQ, 256>>>(x, gnorm);

    // qkv = h @ w_qkv  (2048 x 3072 x 2048)
    sgemm<<<dim3(3072/64, SQ/64), 256>>>(h, w_qkv, nullptr, qkv, SQ, 3072, DIM, 0);
    // comb gates = sigmoid(h @ w_comb + b_comb)   (2048 x 48)
    sgemm<<<dim3(1, SQ/64), 256>>>(h, w_comb, b_comb, comb, SQ, 48, DIM, 3);

    // compression MLPs
    build_win<<<dim3(NW, KV), 256>>>(k_pos, v_pos);
    sgemm<<<dim3(2048/64, (KV*NW + 63)/64), 256>>>(kwf, kc_w1, kc_b1, hid, KV*NW, 2048, 2048, 2);
    sgemm<<<dim3(DH/64,   (KV*NW + 63)/64), 256>>>(hid, kc_w2, kc_b2, craw, KV*NW, DH, 2048, 1);
    assemble_c<<<dim3(NKEYS, KV), 128>>>(mem_kv, 0);
    sgemm<<<dim3(2048/64, (KV*NW + 63)/64), 256>>>(vwf, vc_w1, vc_b1, hid, KV*NW, 2048, 2048, 2);
    sgemm<<<dim3(DH/64,   (KV*NW + 63)/64), 256>>>(hid, vc_w2, vc_b2, craw, KV*NW, DH, 2048, 1);
    assemble_c<<<dim3(NKEYS, KV), 128>>>(mem_kv, 1);

    rope_kernel<<<SQ, 256>>>();

    comp_attn<<<dim3(SQ, KV), 256>>>();
    sel_sw_attn<<<dim3(SQ, KV), 256>>>();

    // final projection: att(2048,2048) @ w_out(2048,2048)
    sgemm<<<dim3(DIM/64, SQ/64), 256>>>(att, w_out, nullptr, out, SQ, DIM, HEADS*DH, 0);
}

// round 4
// speedup vs baseline: 1.4519x; 1.4519x over previous
#include <cuda_runtime.h>
#include <math.h>
#include <stdint.h>

#define SQ    2048      // sequence length
#define DIM   2048
#define HEADS 16
#define KV    4
#define GG    4         // heads per kv head
#define DH    128
#define NW    255       // num compression windows
#define NKEYS 256       // NMEM + NW
#define NF    128       // num selection blocks
#define NSEL  4
#define SBS   16
#define SWIN  64
#define SCALE 0.08838834764831845f   // 1/sqrt(128)

// ---------------- scratch (device globals; no allocations allowed) -------------
__device__ float g_h[SQ*DIM];
__device__ float g_qkv[SQ*3072];
__device__ float g_comb[SQ*48];
__device__ float g_kwflat[KV*NW*2048];
__device__ float g_vwflat[KV*NW*2048];
__device__ float g_hidden[KV*NW*2048];
__device__ float g_craw[KV*NW*DH];
__device__ float g_ck[KV*NKEYS*DH];
__device__ float g_cv[KV*NKEYS*DH];
__device__ float g_rq[SQ*HEADS*DH];
__device__ float g_rk[KV*SQ*DH];
__device__ int   g_sel[KV*SQ*NSEL];
__device__ float g_att[SQ*HEADS*DH];

// ---------------- helpers ----------------
__device__ __forceinline__ float blkmax(float v, float* red, int t) {
    red[t] = v; __syncthreads();
    #pragma unroll
    for (int st = 128; st > 0; st >>= 1) {
        if (t < st) red[t] = fmaxf(red[t], red[t + st]);
        __syncthreads();
    }
    float r = red[0]; __syncthreads();
    return r;
}
__device__ __forceinline__ float blksum(float v, float* red, int t) {
    red[t] = v; __syncthreads();
    #pragma unroll
    for (int st = 128; st > 0; st >>= 1) {
        if (t < st) red[t] += red[t + st];
        __syncthreads();
    }
    float r = red[0]; __syncthreads();
    return r;
}

__device__ __forceinline__ uint32_t f2tf32(float f) {
    uint32_t u;
    asm("cvt.rna.tf32.f32 %0, %1;" : "=r"(u) : "f"(f));
    return u;
}

// split x into hi (tf32) and lo (tf32 of residual)
__device__ __forceinline__ void tf32split(float x, uint32_t& hi, uint32_t& lo) {
    hi = f2tf32(x);
    float r = x - __uint_as_float(hi);
    lo = f2tf32(r);
}

__device__ __forceinline__ void mma_tf32(float* d, const uint32_t* a, const uint32_t* b) {
    asm volatile(
        "mma.sync.aligned.m16n8k8.row.col.f32.tf32.tf32.f32 "
        "{%0,%1,%2,%3}, {%4,%5,%6,%7}, {%8,%9}, {%0,%1,%2,%3};"
        : "+f"(d[0]), "+f"(d[1]), "+f"(d[2]), "+f"(d[3])
        : "r"(a[0]), "r"(a[1]), "r"(a[2]), "r"(a[3]),
          "r"(b[0]), "r"(b[1]));
}

// ---------------- RMSNorm ----------------
__global__ void rmsnorm_kernel(const float* __restrict__ x, const float* __restrict__ g) {
    int s = blockIdx.x;
    int t = threadIdx.x;
    __shared__ float red[256];
    float acc = 0.f;
    for (int i = t; i < DIM; i += 256) { float v = x[s*DIM + i]; acc += v*v; }
    red[t] = acc; __syncthreads();
    for (int st = 128; st > 0; st >>= 1) {
        if (t < st) red[t] += red[t + st];
        __syncthreads();
    }
    float r = rsqrtf(red[0] / (float)DIM + 1e-6f);
    for (int i = t; i < DIM; i += 256) g_h[s*DIM + i] = x[s*DIM + i] * r * g[i];
}

// ---------------- 3xTF32 tensor-core GEMM (fp32-accurate) ----------------
// A(M,K) row-major fp32, B(K,N) row-major fp32, C(M,N) fp32.
// Tile 128x128x32, 256 threads (8 warps), each warp 32x64 (2x8 m16n8k8 mma).
// Each operand split hi/lo; 3 MMAs per fragment: hi*hi + hi*lo + lo*hi.
// Requires: N % 128 == 0, K % 32 == 0. M arbitrary (guarded).
// epi: 0 = none, 1 = +bias, 2 = +bias,relu
#define A_STR 36
#define B_STR 132
#define A_TILE (128*A_STR)
#define B_TILE (32*B_STR)
#define SMEM_DYN_BYTES ((A_TILE*2 + B_TILE*2) * 4)

__global__ void __launch_bounds__(256) tf32gemm(
    const float* __restrict__ A, const float* __restrict__ B,
    const float* __restrict__ bias, float* __restrict__ C,
    int M, int N, int K, int epi)
{
    extern __shared__ uint32_t smem_dyn[];
    uint32_t* AsH = smem_dyn;
    uint32_t* AsL = AsH + A_TILE;
    uint32_t* BsH = AsL + A_TILE;
    uint32_t* BsL = BsH + B_TILE;

    int tid = threadIdx.x;
    int lane = tid & 31;
    int w = tid >> 5;
    int warp_m = w & 3;      // 0..3
    int warp_n = w >> 2;     // 0..1
    int gid = lane >> 2;     // 0..7
    int t4  = lane & 3;      // 0..3

    int row0 = blockIdx.y * 128;
    int col0 = blockIdx.x * 128;

    float acc[2][8][4];
    #pragma unroll
    for (int mf = 0; mf < 2; mf++)
        #pragma unroll
        for (int nf = 0; nf < 8; nf++)
            #pragma unroll
            for (int u = 0; u < 4; u++) acc[mf][nf][u] = 0.f;

    int nk = K >> 5;

    // per-thread gmem load coordinates
    int arow[4], ac4[4], brow[4], bc4[4];
    #pragma unroll
    for (int u = 0; u < 4; u++) {
        int idx = tid + u*256;
        arow[u] = idx >> 3;  ac4[u] = idx & 7;    // A: 128 rows x 8 float4
        brow[u] = idx >> 5;  bc4[u] = idx & 31;   // B: 32 rows x 32 float4
    }

    // stage a tile into smem (split hi/lo)
    auto stage = [&](const float4* pa, const float4* pb) {
        #pragma unroll
        for (int u = 0; u < 4; u++) {
            float vs[4] = {pa[u].x, pa[u].y, pa[u].z, pa[u].w};
            #pragma unroll
            for (int e = 0; e < 4; e++) {
                uint32_t hi, lo; tf32split(vs[e], hi, lo);
                int off = arow[u]*A_STR + ac4[u]*4 + e;
                AsH[off] = hi; AsL[off] = lo;
            }
            float ws[4] = {pb[u].x, pb[u].y, pb[u].z, pb[u].w};
            #pragma unroll
            for (int e = 0; e < 4; e++) {
                uint32_t hi, lo; tf32split(ws[e], hi, lo);
                int off = brow[u]*B_STR + bc4[u]*4 + e;
                BsH[off] = hi; BsL[off] = lo;
            }
        }
    };

    // preload tile 0
    {
        float4 pa[4], pb[4];
        #pragma unroll
        for (int u = 0; u < 4; u++) {
            int gr = row0 + arow[u];
            pa[u] = (gr < M) ? *reinterpret_cast<const float4*>(&A[(long)gr*K + ac4[u]*4])
                             : make_float4(0.f,0.f,0.f,0.f);
            pb[u] = *reinterpret_cast<const float4*>(&B[(long)brow[u]*N + col0 + bc4[u]*4]);
        }
        stage(pa, pb);
    }
    __syncthreads();

    int arb = warp_m * 32;
    int cb  = warp_n * 64;

    for (int kt = 0; kt < nk; kt++) {
        // prefetch next tile into registers
        float4 pa[4], pb[4];
        bool nxt = (kt + 1) < nk;
        if (nxt) {
            int k0 = (kt + 1) << 5;
            #pragma unroll
            for (int u = 0; u < 4; u++) {
                int gr = row0 + arow[u];
                pa[u] = (gr < M) ? *reinterpret_cast<const float4*>(&A[(long)gr*K + k0 + ac4[u]*4])
                                 : make_float4(0.f,0.f,0.f,0.f);
                pb[u] = *reinterpret_cast<const float4*>(&B[(long)(k0 + brow[u])*N + col0 + bc4[u]*4]);
            }
        }

        // compute on current smem tile: 4 k8 steps
        #pragma unroll
        for (int step = 0; step < 4; step++) {
            int ks = step * 8;
            uint32_t afh[2][4], afl[2][4];
            #pragma unroll
            for (int mf = 0; mf < 2; mf++) {
                int r = arb + mf*16 + gid;
                int o0 = r*A_STR + ks + t4;
                int o1 = (r+8)*A_STR + ks + t4;
                afh[mf][0] = AsH[o0];     afl[mf][0] = AsL[o0];
                afh[mf][1] = AsH[o1];     afl[mf][1] = AsL[o1];
                afh[mf][2] = AsH[o0 + 4]; afl[mf][2] = AsL[o0 + 4];
                afh[mf][3] = AsH[o1 + 4]; afl[mf][3] = AsL[o1 + 4];
            }
            uint32_t bfh[8][2], bfl[8][2];
            #pragma unroll
            for (int nf = 0; nf < 8; nf++) {
                int c = cb + nf*8 + gid;
                int o0 = (ks + t4)*B_STR + c;
                int o1 = (ks + t4 + 4)*B_STR + c;
                bfh[nf][0] = BsH[o0]; bfl[nf][0] = BsL[o0];
                bfh[nf][1] = BsH[o1]; bfl[nf][1] = BsL[o1];
            }
            #pragma unroll
            for (int mf = 0; mf < 2; mf++)
                #pragma unroll
                for (int nf = 0; nf < 8; nf++) {
                    mma_tf32(acc[mf][nf], afl[mf], bfh[nf]);   // lo*hi
                    mma_tf32(acc[mf][nf], afh[mf], bfl[nf]);   // hi*lo
                    mma_tf32(acc[mf][nf], afh[mf], bfh[nf]);   // hi*hi
                }
        }

        if (nxt) {
            __syncthreads();
            stage(pa, pb);
            __syncthreads();
        }
    }

    // epilogue
    #pragma unroll
    for (int mf = 0; mf < 2; mf++) {
        #pragma unroll
        for (int nf = 0; nf < 8; nf++) {
            int r0 = row0 + arb + mf*16 + gid;
            int c0 = col0 + cb + nf*8 + 2*t4;
            float b0 = 0.f, b1 = 0.f;
            if (epi >= 1) { b0 = bias[c0]; b1 = bias[c0+1]; }
            if (r0 < M) {
                float v0 = acc[mf][nf][0] + b0;
                float v1 = acc[mf][nf][1] + b1;
                if (epi == 2) { v0 = fmaxf(v0, 0.f); v1 = fmaxf(v1, 0.f); }
                C[(long)r0*N + c0]     = v0;
                C[(long)r0*N + c0 + 1] = v1;
            }
            int r1 = r0 + 8;
            if (r1 < M) {
                float v2 = acc[mf][nf][2] + b0;
                float v3 = acc[mf][nf][3] + b1;
                if (epi == 2) { v2 = fmaxf(v2, 0.f); v3 = fmaxf(v3, 0.f); }
                C[(long)r1*N + c0]     = v2;
                C[(long)r1*N + c0 + 1] = v3;
            }
        }
    }
}

// ---------------- small SIMT SGEMM (for comb, N=48) ----------------
// epi: 3 = +bias,sigmoid
__global__ void sgemm(const float* __restrict__ A, const float* __restrict__ B,
                      const float* __restrict__ bias, float* __restrict__ C,
                      int M, int N, int K, int epi)
{
    __shared__ float As[16][64];
    __shared__ float Bs[16][64];
    int tid = threadIdx.x;
    int row0 = blockIdx.y * 64, col0 = blockIdx.x * 64;
    int tr = tid >> 4, tc = tid & 15;
    float acc[4][4] = {};
    for (int k0 = 0; k0 < K; k0 += 16) {
        #pragma unroll
        for (int i = 0; i < 4; i++) {
            int idx = tid + i * 256;
            int r = idx >> 4, c = idx & 15;
            int gr = row0 + r;
            As[c][r] = (gr < M) ? A[gr * K + k0 + c] : 0.f;
            int br = idx >> 6, bc = idx & 63;
            int gc = col0 + bc;
            Bs[br][bc] = (gc < N) ? B[(k0 + br) * N + gc] : 0.f;
        }
        __syncthreads();
        #pragma unroll
        for (int kk = 0; kk < 16; kk++) {
            float a[4], b[4];
            #pragma unroll
            for (int u = 0; u < 4; u++) { a[u] = As[kk][tr*4 + u]; b[u] = Bs[kk][tc*4 + u]; }
            #pragma unroll
            for (int i = 0; i < 4; i++)
                #pragma unroll
                for (int j = 0; j < 4; j++)
                    acc[i][j] = fmaf(a[i], b[j], acc[i][j]);
        }
        __syncthreads();
    }
    #pragma unroll
    for (int i = 0; i < 4; i++) {
        int r = row0 + tr*4 + i;
        if (r >= M) continue;
        #pragma unroll
        for (int j = 0; j < 4; j++) {
            int c = col0 + tc*4 + j;
            if (c >= N) continue;
            float v = acc[i][j];
            if (epi >= 1) {
                v += bias[c];
                if (epi == 2) v = fmaxf(v, 0.f);
                else if (epi == 3) v = 1.f / (1.f + expf(-v));
            }
            C[r * N + c] = v;
        }
    }
}

// ---------------- window gather + positional add ----------------
__global__ void build_win(const float* __restrict__ k_pos, const float* __restrict__ v_pos) {
    int w = blockIdx.x, kh = blockIdx.y;
    int row = kh * NW + w;
    for (int i = threadIdx.x; i < 2048; i += 256) {
        int c = i >> 7, d = i & 127;
        int s = w * 8 + c;
        g_kwflat[row*2048 + i] = g_qkv[s*3072 + 2048 + kh*DH + d] + k_pos[kh*2048 + i];
        g_vwflat[row*2048 + i] = g_qkv[s*3072 + 2560 + kh*DH + d] + v_pos[kh*2048 + i];
    }
}

// ---------------- assemble ck / cv (prepend memory token) ----------------
__global__ void assemble_c(const float* __restrict__ mem_kv, int which) {
    int j = blockIdx.x, kh = blockIdx.y;
    int d = threadIdx.x; // 128
    float v;
    if (j == 0) v = mem_kv[which * (KV*DH) + kh*DH + d];
    else        v = g_craw[(kh*NW + (j-1))*DH + d];
    float* dst = which ? g_cv : g_ck;
    dst[(kh*NKEYS + j)*DH + d] = v;
}

// ---------------- RoPE for q (16 heads) and k (4 heads) ----------------
__global__ void rope_kernel() {
    int s = blockIdx.x;
    for (int p = threadIdx.x; p < 20 * 64; p += 256) {
        int head = p >> 6;
        int i = p & 63;
        float invf = 1.0f / powf(10000.0f, (float)i * (1.0f / 64.0f));
        float ang = (float)s * invf;
        float sn, cs;
        sincosf(ang, &sn, &cs);
        if (head < HEADS) {
            const float* src = &g_qkv[s*3072 + head*DH];
            float t1 = src[2*i], t2 = src[2*i + 1];
            float* dst = &g_rq[(s*HEADS + head)*DH];
            dst[2*i]     = t1*cs - t2*sn;
            dst[2*i + 1] = t1*sn + t2*cs;
        } else {
            int kh = head - HEADS;
            const float* src = &g_qkv[s*3072 + 2048 + kh*DH];
            float t1 = src[2*i], t2 = src[2*i + 1];
            float* dst = &g_rk[(kh*SQ + s)*DH];
            dst[2*i]     = t1*cs - t2*sn;
            dst[2*i + 1] = t1*sn + t2*cs;
        }
    }
}

// ---------------- compressed attention + importance + top-k ----------------
__global__ void comp_attn() {
    int q = blockIdx.x, kv = blockIdx.y;
    int t = threadIdx.x;
    __shared__ __align__(16) float qs[4][DH];
    __shared__ float sim[4][NKEYS];
    __shared__ float red[256];
    __shared__ float impsh[NF];

    for (int i = t; i < 4*DH; i += 256) {
        int g = i >> 7, d = i & 127;
        qs[g][d] = g_qkv[q*3072 + (kv*GG + g)*DH + d];
    }
    __syncthreads();

    {
        int j = t;
        const float4* kr = reinterpret_cast<const float4*>(&g_ck[(kv*NKEYS + j)*DH]);
        const float4* q0 = reinterpret_cast<const float4*>(qs[0]);
        const float4* q1 = reinterpret_cast<const float4*>(qs[1]);
        const float4* q2 = reinterpret_cast<const float4*>(qs[2]);
        const float4* q3 = reinterpret_cast<const float4*>(qs[3]);
        float s0=0,s1=0,s2=0,s3=0;
        #pragma unroll 8
        for (int d4 = 0; d4 < 32; d4++) {
            float4 b = kr[d4]; float4 a;
            a = q0[d4]; s0 += a.x*b.x + a.y*b.y + a.z*b.z + a.w*b.w;
            a = q1[d4]; s1 += a.x*b.x + a.y*b.y + a.z*b.z + a.w*b.w;
            a = q2[d4]; s2 += a.x*b.x + a.y*b.y + a.z*b.z + a.w*b.w;
            a = q3[d4]; s3 += a.x*b.x + a.y*b.y + a.z*b.z + a.w*b.w;
        }
        bool valid = (j == 0) || (q > (j - 1) * 8 + 15);
        sim[0][j] = valid ? s0*SCALE : -INFINITY;
        sim[1][j] = valid ? s1*SCALE : -INFINITY;
        sim[2][j] = valid ? s2*SCALE : -INFINITY;
        sim[3][j] = valid ? s3*SCALE : -INFINITY;
    }
    __syncthreads();

    for (int g = 0; g < 4; g++) {
        float v = sim[g][t];
        float m = blkmax(v, red, t);
        float e = expf(v - m);
        float s = blksum(e, red, t);
        sim[g][t] = e / s;
        __syncthreads();
    }

    for (int p = t; p < 512; p += 256) {
        int g = p >> 7, d = p & 127;
        float acc = 0.f;
        const float* cvp = &g_cv[kv*NKEYS*DH + d];
        for (int j = 0; j < NKEYS; j++) acc += sim[g][j] * cvp[j*DH];
        int head = kv*GG + g;
        g_att[(q*HEADS + head)*DH + d] = g_comb[q*48 + head*3 + 0] * acc;
    }

    if (t < NF) {
        int f = t;
        float a = 0.f;
        #pragma unroll
        for (int g = 0; g < 4; g++) {
            a += sim[g][1 + 2*f];
            if (2*f + 1 < NW) a += sim[g][2 + 2*f];
        }
        impsh[f] = (f < (q >> 4)) ? a * 0.125f : -1.0f;
    }
    __syncthreads();
    if (t == 0) {
        for (int it = 0; it < NSEL; it++) {
            float best = -1e30f; int bi = 0;
            for (int f = 0; f < NF; f++)
                if (impsh[f] > best) { best = impsh[f]; bi = f; }
            g_sel[(kv*SQ + q)*NSEL + it] = (best > 0.f) ? bi : -1;
            impsh[bi] = -1e30f;
        }
    }
}

// ---------------- selected + sliding window attention ----------------
__global__ void sel_sw_attn() {
    int q = blockIdx.x, kv = blockIdx.y;
    int t = threadIdx.x;
    __shared__ __align__(16) float qs[4][DH];
    __shared__ float fs[4][80];
    __shared__ float ws[4][65];
    __shared__ int   kp[80];
    __shared__ float red[256];

    for (int i = t; i < 4*DH; i += 256) {
        int g = i >> 7, d = i & 127;
        qs[g][d] = g_rq[(q*HEADS + kv*GG + g)*DH + d];
    }
    if (t < 80) {
        int pos, valid;
        if (t < 64) {
            int blk = g_sel[(kv*SQ + q)*NSEL + (t >> 4)];
            pos = blk*SBS + (t & 15);
            valid = (blk >= 0) && (pos <= q);
        } else {
            pos = (q & ~(SBS-1)) + (t - 64);
            valid = (pos <= q);
        }
        kp[t] = valid ? pos : -1;
    }
    __syncthreads();

    int kbase = (q >= SWIN) ? (q - SWIN) : 0;
    int cnt = q - kbase + 1;

    if (t < 80) {
        int pos = kp[t];
        float a0=-INFINITY,a1=-INFINITY,a2=-INFINITY,a3=-INFINITY;
        if (pos >= 0) {
            const float4* kr = reinterpret_cast<const float4*>(&g_rk[(kv*SQ + pos)*DH]);
            const float4* q0 = reinterpret_cast<const float4*>(qs[0]);
            const float4* q1 = reinterpret_cast<const float4*>(qs[1]);
            const float4* q2 = reinterpret_cast<const float4*>(qs[2]);
            const float4* q3 = reinterpret_cast<const float4*>(qs[3]);
            float s0=0,s1=0,s2=0,s3=0;
            #pragma unroll 8
            for (int d4 = 0; d4 < 32; d4++) {
                float4 b = kr[d4]; float4 a;
                a = q0[d4]; s0 += a.x*b.x + a.y*b.y + a.z*b.z + a.w*b.w;
                a = q1[d4]; s1 += a.x*b.x + a.y*b.y + a.z*b.z + a.w*b.w;
                a = q2[d4]; s2 += a.x*b.x + a.y*b.y + a.z*b.z + a.w*b.w;
                a = q3[d4]; s3 += a.x*b.x + a.y*b.y + a.z*b.z + a.w*b.w;
            }
            a0 = s0*SCALE; a1 = s1*SCALE; a2 = s2*SCALE; a3 = s3*SCALE;
        }
        fs[0][t]=a0; fs[1][t]=a1; fs[2][t]=a2; fs[3][t]=a3;
    }
    if (t >= 128 && t < 193) {
        int j = t - 128;
        float a0=-INFINITY,a1=-INFINITY,a2=-INFINITY,a3=-INFINITY;
        if (j < cnt) {
            int pos = kbase + j;
            const float4* kr = reinterpret_cast<const float4*>(&g_rk[(kv*SQ + pos)*DH]);
            const float4* q0 = reinterpret_cast<const float4*>(qs[0]);
            const float4* q1 = reinterpret_cast<const float4*>(qs[1]);
            const float4* q2 = reinterpret_cast<const float4*>(qs[2]);
            const float4* q3 = reinterpret_cast<const float4*>(qs[3]);
            float s0=0,s1=0,s2=0,s3=0;
            #pragma unroll 8
            for (int d4 = 0; d4 < 32; d4++) {
                float4 b = kr[d4]; float4 a;
                a = q0[d4]; s0 += a.x*b.x + a.y*b.y + a.z*b.z + a.w*b.w;
                a = q1[d4]; s1 += a.x*b.x + a.y*b.y + a.z*b.z + a.w*b.w;
                a = q2[d4]; s2 += a.x*b.x + a.y*b.y + a.z*b.z + a.w*b.w;
                a = q3[d4]; s3 += a.x*b.x + a.y*b.y + a.z*b.z + a.w*b.w;
            }
            a0 = s0*SCALE; a1 = s1*SCALE; a2 = s2*SCALE; a3 = s3*SCALE;
        }
        ws[0][j]=a0; ws[1][j]=a1; ws[2][j]=a2; ws[3][j]=a3;
    }
    __syncthreads();

    for (int g = 0; g < 4; g++) {
        float v = (t < 80) ? fs[g][t] : -INFINITY;
        float m = blkmax(v, red, t);
        float e = (t < 80) ? expf(v - m) : 0.f;
        float s = blksum(e, red, t);
        if (t < 80) fs[g][t] = e / s;
        float v2 = (t < 65) ? ws[g][t] : -INFINITY;
        float m2 = blkmax(v2, red, t);
        float e2 = (t < 65) ? expf(v2 - m2) : 0.f;
        float s2 = blksum(e2, red, t);
        if (t < 65) ws[g][t] = e2 / s2;
        __syncthreads();
    }

    for (int p = t; p < 512; p += 256) {
        int g = p >> 7, d = p & 127;
        float fa = 0.f;
        for (int j = 0; j < 80; j++) {
            int pos = kp[j];
            if (pos >= 0) fa += fs[g][j] * g_qkv[pos*3072 + 2560 + kv*DH + d];
        }
        float wa = 0.f;
        for (int j = 0; j < cnt; j++)
            wa += ws[g][j] * g_qkv[(kbase + j)*3072 + 2560 + kv*DH + d];
        int head = kv*GG + g;
        float g1 = g_comb[q*48 + head*3 + 1];
        float g2 = g_comb[q*48 + head*3 + 2];
        g_att[(q*HEADS + head)*DH + d] += g1*fa + g2*wa;
    }
}

// ---------------- launcher ----------------
extern "C" void kernel_launch(void* const* d_in, const int* in_sizes, int n_in,
                              void* d_out, int out_size) {
    const float* x      = (const float*)d_in[0];
    const float* gnorm  = (const float*)d_in[1];
    const float* w_qkv  = (const float*)d_in[2];
    const float* k_pos  = (const float*)d_in[3];
    const float* v_pos  = (const float*)d_in[4];
    const float* mem_kv = (const float*)d_in[5];
    const float* kc_w1  = (const float*)d_in[6];
    const float* kc_b1  = (const float*)d_in[7];
    const float* kc_w2  = (const float*)d_in[8];
    const float* kc_b2  = (const float*)d_in[9];
    const float* vc_w1  = (const float*)d_in[10];
    const float* vc_b1  = (const float*)d_in[11];
    const float* vc_w2  = (const float*)d_in[12];
    const float* vc_b2  = (const float*)d_in[13];
    const float* w_comb = (const float*)d_in[14];
    const float* b_comb = (const float*)d_in[15];
    const float* w_out  = (const float*)d_in[16];
    float* out = (float*)d_out;

    float *h, *qkv, *comb, *kwf, *vwf, *hid, *craw, *att;
    cudaGetSymbolAddress((void**)&h,    g_h);
    cudaGetSymbolAddress((void**)&qkv,  g_qkv);
    cudaGetSymbolAddress((void**)&comb, g_comb);
    cudaGetSymbolAddress((void**)&kwf,  g_kwflat);
    cudaGetSymbolAddress((void**)&vwf,  g_vwflat);
    cudaGetSymbolAddress((void**)&hid,  g_hidden);
    cudaGetSymbolAddress((void**)&craw, g_craw);
    cudaGetSymbolAddress((void**)&att,  g_att);

    static bool attr_set = false;
    if (!attr_set) {
        cudaFuncSetAttribute(tf32gemm, cudaFuncAttributeMaxDynamicSharedMemorySize, SMEM_DYN_BYTES);
        attr_set = true;
    }

    rmsnorm_kernel<<<SQ, 256>>>(x, gnorm);

    // qkv = h @ w_qkv  (2048 x 3072 x 2048)
    tf32gemm<<<dim3(3072/128, SQ/128), 256, SMEM_DYN_BYTES>>>(h, w_qkv, nullptr, qkv, SQ, 3072, DIM, 0);
    // comb gates = sigmoid(h @ w_comb + b_comb)   (2048 x 48)
    sgemm<<<dim3(1, SQ/64), 256>>>(h, w_comb, b_comb, comb, SQ, 48, DIM, 3);

    // compression MLPs
    build_win<<<dim3(NW, KV), 256>>>(k_pos, v_pos);
    tf32gemm<<<dim3(2048/128, (KV*NW + 127)/128), 256, SMEM_DYN_BYTES>>>(kwf, kc_w1, kc_b1, hid, KV*NW, 2048, 2048, 2);
    tf32gemm<<<dim3(1,        (KV*NW + 127)/128), 256, SMEM_DYN_BYTES>>>(hid, kc_w2, kc_b2, craw, KV*NW, DH, 2048, 1);
    assemble_c<<<dim3(NKEYS, KV), 128>>>(mem_kv, 0);
    tf32gemm<<<dim3(2048/128, (KV*NW + 127)/128), 256, SMEM_DYN_BYTES>>>(vwf, vc_w1, vc_b1, hid, KV*NW, 2048, 2048, 2);
    tf32gemm<<<dim3(1,        (KV*NW + 127)/128), 256, SMEM_DYN_BYTES>>>(hid, vc_w2, vc_b2, craw, KV*NW, DH, 2048, 1);
    assemble_c<<<dim3(NKEYS, KV), 128>>>(mem_kv, 1);

    rope_kernel<<<SQ, 256>>>();

    comp_attn<<<dim3(SQ, KV), 256>>>();
    sel_sw_attn<<<dim3(SQ, KV), 256>>>();

    // final projection: att(2048,2048) @ w_out(2048,2048)
    tf32gemm<<<dim3(DIM/128, SQ/128), 256, SMEM_DYN_BYTES>>>(att, w_out, nullptr, out, SQ, DIM, HEADS*DH, 0);
}

// round 5
// speedup vs baseline: 2.1007x; 1.4469x over previous
#include <cuda_runtime.h>
#include <cuda_bf16.h>
#include <math.h>
#include <stdint.h>

#define SQ    2048      // sequence length
#define DIM   2048
#define HEADS 16
#define KV    4
#define GG    4         // heads per kv head
#define DH    128
#define NW    255       // num compression windows
#define NKEYS 256       // NMEM + NW
#define NF    128       // num selection blocks
#define NSEL  4
#define SBS   16
#define SWIN  64
#define SCALE 0.08838834764831845f   // 1/sqrt(128)

#define KSPLIT 8        // split-K factor for the small-N MLP layer-2 GEMMs

// ---------------- scratch (device globals; no allocations allowed) -------------
__device__ float g_h[SQ*DIM];
__device__ float g_qkv[SQ*3072];
__device__ float g_comb[SQ*48];
__device__ float g_kwflat[KV*NW*2048];
__device__ float g_vwflat[KV*NW*2048];
__device__ float g_hidden[KV*NW*2048];
__device__ float g_craw[KV*NW*DH];
__device__ float g_part[KSPLIT*KV*NW*DH];   // split-K partials
__device__ float g_ck[KV*NKEYS*DH];
__device__ float g_cv[KV*NKEYS*DH];
__device__ float g_rq[SQ*HEADS*DH];
__device__ float g_rk[KV*SQ*DH];
__device__ int   g_sel[KV*SQ*NSEL];
__device__ float g_att[SQ*HEADS*DH];

// ---------------- helpers ----------------
__device__ __forceinline__ float blkmax(float v, float* red, int t) {
    red[t] = v; __syncthreads();
    #pragma unroll
    for (int st = 128; st > 0; st >>= 1) {
        if (t < st) red[t] = fmaxf(red[t], red[t + st]);
        __syncthreads();
    }
    float r = red[0]; __syncthreads();
    return r;
}
__device__ __forceinline__ float blksum(float v, float* red, int t) {
    red[t] = v; __syncthreads();
    #pragma unroll
    for (int st = 128; st > 0; st >>= 1) {
        if (t < st) red[t] += red[t + st];
        __syncthreads();
    }
    float r = red[0]; __syncthreads();
    return r;
}

// pack two floats into bf16x2 (low half = f0)
__device__ __forceinline__ uint32_t pack_bf16x2(float f0, float f1) {
    uint32_t r;
    asm("cvt.rn.bf16x2.f32 %0, %1, %2;" : "=r"(r) : "f"(f1), "f"(f0));
    return r;
}
// split two floats into hi-bf16x2 and lo-bf16x2
__device__ __forceinline__ void split2(float f0, float f1, uint32_t& hi, uint32_t& lo) {
    hi = pack_bf16x2(f0, f1);
    float h0 = __uint_as_float((hi & 0xFFFFu) << 16);
    float h1 = __uint_as_float(hi & 0xFFFF0000u);
    lo = pack_bf16x2(f0 - h0, f1 - h1);
}

__device__ __forceinline__ void mma_bf16(float* d, const uint32_t* a, const uint32_t* b) {
    asm volatile(
        "mma.sync.aligned.m16n8k16.row.col.f32.bf16.bf16.f32 "
        "{%0,%1,%2,%3}, {%4,%5,%6,%7}, {%8,%9}, {%0,%1,%2,%3};"
        : "+f"(d[0]), "+f"(d[1]), "+f"(d[2]), "+f"(d[3])
        : "r"(a[0]), "r"(a[1]), "r"(a[2]), "r"(a[3]),
          "r"(b[0]), "r"(b[1]));
}

// ---------------- RMSNorm ----------------
__global__ void rmsnorm_kernel(const float* __restrict__ x, const float* __restrict__ g) {
    int s = blockIdx.x;
    int t = threadIdx.x;
    __shared__ float red[256];
    float acc = 0.f;
    for (int i = t; i < DIM; i += 256) { float v = x[s*DIM + i]; acc += v*v; }
    red[t] = acc; __syncthreads();
    for (int st = 128; st > 0; st >>= 1) {
        if (t < st) red[t] += red[t + st];
        __syncthreads();
    }
    float r = rsqrtf(red[0] / (float)DIM + 1e-6f);
    for (int i = t; i < DIM; i += 256) g_h[s*DIM + i] = x[s*DIM + i] * r * g[i];
}

// ---------------- split-BF16 tensor-core GEMM (≈fp32-accurate) ----------------
// A(M,K) row-major fp32, B(K,N) row-major fp32, C(M,N) fp32.
// CTA tile 128x128x32, 256 threads (8 warps), warp tile 32x64.
// Each value split into hi/lo bf16; 3 MMAs: hi*hi + hi*lo + lo*hi (m16n8k16).
// Requires: N % 128 == 0, K % 32 == 0, kslice % 32 == 0. M arbitrary (guarded).
// epi: 0 = none, 1 = +bias, 2 = +bias,relu
// If gridDim.z > 1: each z computes K range [z*kslice,(z+1)*kslice) and writes
// a raw partial to C[z*M*N + ...] (epi ignored).
#define A_STR 20     // words per A row (16 data + 4 pad)
#define B_STR 136    // words per B k-pair row (128 data + 8 pad)

__global__ void __launch_bounds__(256) bfgemm(
    const float* __restrict__ A, const float* __restrict__ B,
    const float* __restrict__ bias, float* __restrict__ C,
    int M, int N, int K, int epi, int kslice)
{
    __shared__ uint32_t AH[128*A_STR];
    __shared__ uint32_t AL[128*A_STR];
    __shared__ uint32_t BH[16*B_STR];
    __shared__ uint32_t BL[16*B_STR];

    int tid = threadIdx.x;
    int lane = tid & 31;
    int w = tid >> 5;
    int warp_m = w & 3;      // 0..3
    int warp_n = w >> 2;     // 0..1
    int gid = lane >> 2;     // 0..7
    int t4  = lane & 3;      // 0..3

    int row0 = blockIdx.y * 128;
    int col0 = blockIdx.x * 128;
    int kbeg = blockIdx.z * kslice;
    int nk = kslice >> 5;

    float acc[2][8][4];
    #pragma unroll
    for (int mf = 0; mf < 2; mf++)
        #pragma unroll
        for (int nf = 0; nf < 8; nf++)
            #pragma unroll
            for (int u = 0; u < 4; u++) acc[mf][nf][u] = 0.f;

    // A staging coords: idx = tid + u*256 (u<4): row = idx>>3, f4 = idx&7
    int ar = tid >> 3, af4 = tid & 7;      // +32 rows per u
    // B staging coords: idx = tid + u*256 (u<2): kp = idx>>5, c4 = idx&31
    int bkp = tid >> 5, bc4 = tid & 31;    // +8 kp per u

    auto stage = [&](const float4* pa, const float4* pb0, const float4* pb1) {
        #pragma unroll
        for (int u = 0; u < 4; u++) {
            int r = ar + u*32;
            uint32_t h0, l0, h1, l1;
            split2(pa[u].x, pa[u].y, h0, l0);
            split2(pa[u].z, pa[u].w, h1, l1);
            int off = r*A_STR + af4*2;
            *reinterpret_cast<uint2*>(&AH[off]) = make_uint2(h0, h1);
            *reinterpret_cast<uint2*>(&AL[off]) = make_uint2(l0, l1);
        }
        #pragma unroll
        for (int u = 0; u < 2; u++) {
            int kp = bkp + u*8;
            const float* r0 = reinterpret_cast<const float*>(&pb0[u]);
            const float* r1 = reinterpret_cast<const float*>(&pb1[u]);
            uint32_t hh[4], ll[4];
            #pragma unroll
            for (int j = 0; j < 4; j++) split2(r0[j], r1[j], hh[j], ll[j]);
            int off = kp*B_STR + bc4*4;
            *reinterpret_cast<uint4*>(&BH[off]) = make_uint4(hh[0], hh[1], hh[2], hh[3]);
            *reinterpret_cast<uint4*>(&BL[off]) = make_uint4(ll[0], ll[1], ll[2], ll[3]);
        }
    };

    auto loadg = [&](int k0, float4* pa, float4* pb0, float4* pb1) {
        #pragma unroll
        for (int u = 0; u < 4; u++) {
            int gr = row0 + ar + u*32;
            pa[u] = (gr < M) ? *reinterpret_cast<const float4*>(&A[(long)gr*K + k0 + af4*4])
                             : make_float4(0.f,0.f,0.f,0.f);
        }
        #pragma unroll
        for (int u = 0; u < 2; u++) {
            int kk = k0 + (bkp + u*8)*2;
            pb0[u] = *reinterpret_cast<const float4*>(&B[(long)kk*N + col0 + bc4*4]);
            pb1[u] = *reinterpret_cast<const float4*>(&B[(long)(kk+1)*N + col0 + bc4*4]);
        }
    };

    {   // preload tile 0
        float4 pa[4], pb0[2], pb1[2];
        loadg(kbeg, pa, pb0, pb1);
        stage(pa, pb0, pb1);
    }
    __syncthreads();

    int arb = warp_m * 32;
    int cb  = warp_n * 64;

    for (int kt = 0; kt < nk; kt++) {
        float4 pa[4], pb0[2], pb1[2];
        bool nxt = (kt + 1) < nk;
        if (nxt) loadg(kbeg + ((kt + 1) << 5), pa, pb0, pb1);

        #pragma unroll
        for (int s = 0; s < 2; s++) {
            uint32_t ah[2][4], al[2][4];
            #pragma unroll
            for (int mf = 0; mf < 2; mf++) {
                int r = arb + mf*16 + gid;
                int o0 = r*A_STR + s*8 + t4;
                int o1 = (r+8)*A_STR + s*8 + t4;
                ah[mf][0] = AH[o0];   al[mf][0] = AL[o0];
                ah[mf][1] = AH[o1];   al[mf][1] = AL[o1];
                ah[mf][2] = AH[o0+4]; al[mf][2] = AL[o0+4];
                ah[mf][3] = AH[o1+4]; al[mf][3] = AL[o1+4];
            }
            uint32_t bh[8][2], bl[8][2];
            #pragma unroll
            for (int nf = 0; nf < 8; nf++) {
                int c = cb + nf*8 + gid;
                int o0 = (s*8 + t4)*B_STR + c;
                int o1 = o0 + 4*B_STR;
                bh[nf][0] = BH[o0]; bl[nf][0] = BL[o0];
                bh[nf][1] = BH[o1]; bl[nf][1] = BL[o1];
            }
            #pragma unroll
            for (int mf = 0; mf < 2; mf++)
                #pragma unroll
                for (int nf = 0; nf < 8; nf++) {
                    mma_bf16(acc[mf][nf], al[mf], bh[nf]);   // lo*hi
                    mma_bf16(acc[mf][nf], ah[mf], bl[nf]);   // hi*lo
                    mma_bf16(acc[mf][nf], ah[mf], bh[nf]);   // hi*hi
                }
        }

        if (nxt) {
            __syncthreads();
            stage(pa, pb0, pb1);
            __syncthreads();
        }
    }

    // epilogue
    bool partial = (gridDim.z > 1);
    float* Cout = partial ? (C + (long)blockIdx.z * M * N) : C;
    #pragma unroll
    for (int mf = 0; mf < 2; mf++) {
        #pragma unroll
        for (int nf = 0; nf < 8; nf++) {
            int r0 = row0 + arb + mf*16 + gid;
            int c0 = col0 + cb + nf*8 + 2*t4;
            float b0 = 0.f, b1 = 0.f;
            if (!partial && epi >= 1) { b0 = bias[c0]; b1 = bias[c0+1]; }
            if (r0 < M) {
                float v0 = acc[mf][nf][0] + b0;
                float v1 = acc[mf][nf][1] + b1;
                if (!partial && epi == 2) { v0 = fmaxf(v0, 0.f); v1 = fmaxf(v1, 0.f); }
                Cout[(long)r0*N + c0]     = v0;
                Cout[(long)r0*N + c0 + 1] = v1;
            }
            int r1 = r0 + 8;
            if (r1 < M) {
                float v2 = acc[mf][nf][2] + b0;
                float v3 = acc[mf][nf][3] + b1;
                if (!partial && epi == 2) { v2 = fmaxf(v2, 0.f); v3 = fmaxf(v3, 0.f); }
                Cout[(long)r1*N + c0]     = v2;
                Cout[(long)r1*N + c0 + 1] = v3;
            }
        }
    }
}

// reduce split-K partials: out = sum_z part[z] + bias
__global__ void splitk_reduce(const float* __restrict__ part, const float* __restrict__ bias,
                              float* __restrict__ out, int M, int N) {
    int i = blockIdx.x * 256 + threadIdx.x;
    if (i >= M * N) return;
    float a = 0.f;
    #pragma unroll
    for (int z = 0; z < KSPLIT; z++) a += part[(long)z*M*N + i];
    out[i] = a + bias[i % N];
}

// ---------------- small SIMT SGEMM (for comb, N=48) ----------------
// epi: 3 = +bias,sigmoid
__global__ void sgemm(const float* __restrict__ A, const float* __restrict__ B,
                      const float* __restrict__ bias, float* __restrict__ C,
                      int M, int N, int K, int epi)
{
    __shared__ float As[16][64];
    __shared__ float Bs[16][64];
    int tid = threadIdx.x;
    int row0 = blockIdx.y * 64, col0 = blockIdx.x * 64;
    int tr = tid >> 4, tc = tid & 15;
    float acc[4][4] = {};
    for (int k0 = 0; k0 < K; k0 += 16) {
        #pragma unroll
        for (int i = 0; i < 4; i++) {
            int idx = tid + i * 256;
            int r = idx >> 4, c = idx & 15;
            int gr = row0 + r;
            As[c][r] = (gr < M) ? A[gr * K + k0 + c] : 0.f;
            int br = idx >> 6, bc = idx & 63;
            int gc = col0 + bc;
            Bs[br][bc] = (gc < N) ? B[(k0 + br) * N + gc] : 0.f;
        }
        __syncthreads();
        #pragma unroll
        for (int kk = 0; kk < 16; kk++) {
            float a[4], b[4];
            #pragma unroll
            for (int u = 0; u < 4; u++) { a[u] = As[kk][tr*4 + u]; b[u] = Bs[kk][tc*4 + u]; }
            #pragma unroll
            for (int i = 0; i < 4; i++)
                #pragma unroll
                for (int j = 0; j < 4; j++)
                    acc[i][j] = fmaf(a[i], b[j], acc[i][j]);
        }
        __syncthreads();
    }
    #pragma unroll
    for (int i = 0; i < 4; i++) {
        int r = row0 + tr*4 + i;
        if (r >= M) continue;
        #pragma unroll
        for (int j = 0; j < 4; j++) {
            int c = col0 + tc*4 + j;
            if (c >= N) continue;
            float v = acc[i][j];
            if (epi >= 1) {
                v += bias[c];
                if (epi == 2) v = fmaxf(v, 0.f);
                else if (epi == 3) v = 1.f / (1.f + expf(-v));
            }
            C[r * N + c] = v;
        }
    }
}

// ---------------- window gather + positional add ----------------
__global__ void build_win(const float* __restrict__ k_pos, const float* __restrict__ v_pos) {
    int w = blockIdx.x, kh = blockIdx.y;
    int row = kh * NW + w;
    for (int i = threadIdx.x; i < 2048; i += 256) {
        int c = i >> 7, d = i & 127;
        int s = w * 8 + c;
        g_kwflat[row*2048 + i] = g_qkv[s*3072 + 2048 + kh*DH + d] + k_pos[kh*2048 + i];
        g_vwflat[row*2048 + i] = g_qkv[s*3072 + 2560 + kh*DH + d] + v_pos[kh*2048 + i];
    }
}

// ---------------- assemble ck / cv (prepend memory token) ----------------
__global__ void assemble_c(const float* __restrict__ mem_kv, int which) {
    int j = blockIdx.x, kh = blockIdx.y;
    int d = threadIdx.x; // 128
    float v;
    if (j == 0) v = mem_kv[which * (KV*DH) + kh*DH + d];
    else        v = g_craw[(kh*NW + (j-1))*DH + d];
    float* dst = which ? g_cv : g_ck;
    dst[(kh*NKEYS + j)*DH + d] = v;
}

// ---------------- RoPE for q (16 heads) and k (4 heads) ----------------
__global__ void rope_kernel() {
    int s = blockIdx.x;
    for (int p = threadIdx.x; p < 20 * 64; p += 256) {
        int head = p >> 6;
        int i = p & 63;
        float invf = 1.0f / powf(10000.0f, (float)i * (1.0f / 64.0f));
        float ang = (float)s * invf;
        float sn, cs;
        sincosf(ang, &sn, &cs);
        if (head < HEADS) {
            const float* src = &g_qkv[s*3072 + head*DH];
            float t1 = src[2*i], t2 = src[2*i + 1];
            float* dst = &g_rq[(s*HEADS + head)*DH];
            dst[2*i]     = t1*cs - t2*sn;
            dst[2*i + 1] = t1*sn + t2*cs;
        } else {
            int kh = head - HEADS;
            const float* src = &g_qkv[s*3072 + 2048 + kh*DH];
            float t1 = src[2*i], t2 = src[2*i + 1];
            float* dst = &g_rk[(kh*SQ + s)*DH];
            dst[2*i]     = t1*cs - t2*sn;
            dst[2*i + 1] = t1*sn + t2*cs;
        }
    }
}

// ---------------- compressed attention + importance + top-k ----------------
__global__ void comp_attn() {
    int q = blockIdx.x, kv = blockIdx.y;
    int t = threadIdx.x;
    __shared__ __align__(16) float qs[4][DH];
    __shared__ float sim[4][NKEYS];
    __shared__ float red[256];
    __shared__ float impsh[NF];

    for (int i = t; i < 4*DH; i += 256) {
        int g = i >> 7, d = i & 127;
        qs[g][d] = g_qkv[q*3072 + (kv*GG + g)*DH + d];
    }
    __syncthreads();

    {
        int j = t;
        const float4* kr = reinterpret_cast<const float4*>(&g_ck[(kv*NKEYS + j)*DH]);
        const float4* q0 = reinterpret_cast<const float4*>(qs[0]);
        const float4* q1 = reinterpret_cast<const float4*>(qs[1]);
        const float4* q2 = reinterpret_cast<const float4*>(qs[2]);
        const float4* q3 = reinterpret_cast<const float4*>(qs[3]);
        float s0=0,s1=0,s2=0,s3=0;
        #pragma unroll 8
        for (int d4 = 0; d4 < 32; d4++) {
            float4 b = kr[d4]; float4 a;
            a = q0[d4]; s0 += a.x*b.x + a.y*b.y + a.z*b.z + a.w*b.w;
            a = q1[d4]; s1 += a.x*b.x + a.y*b.y + a.z*b.z + a.w*b.w;
            a = q2[d4]; s2 += a.x*b.x + a.y*b.y + a.z*b.z + a.w*b.w;
            a = q3[d4]; s3 += a.x*b.x + a.y*b.y + a.z*b.z + a.w*b.w;
        }
        bool valid = (j == 0) || (q > (j - 1) * 8 + 15);
        sim[0][j] = valid ? s0*SCALE : -INFINITY;
        sim[1][j] = valid ? s1*SCALE : -INFINITY;
        sim[2][j] = valid ? s2*SCALE : -INFINITY;
        sim[3][j] = valid ? s3*SCALE : -INFINITY;
    }
    __syncthreads();

    for (int g = 0; g < 4; g++) {
        float v = sim[g][t];
        float m = blkmax(v, red, t);
        float e = expf(v - m);
        float s = blksum(e, red, t);
        sim[g][t] = e / s;
        __syncthreads();
    }

    for (int p = t; p < 512; p += 256) {
        int g = p >> 7, d = p & 127;
        float acc = 0.f;
        const float* cvp = &g_cv[kv*NKEYS*DH + d];
        for (int j = 0; j < NKEYS; j++) acc += sim[g][j] * cvp[j*DH];
        int head = kv*GG + g;
        g_att[(q*HEADS + head)*DH + d] = g_comb[q*48 + head*3 + 0] * acc;
    }

    if (t < NF) {
        int f = t;
        float a = 0.f;
        #pragma unroll
        for (int g = 0; g < 4; g++) {
            a += sim[g][1 + 2*f];
            if (2*f + 1 < NW) a += sim[g][2 + 2*f];
        }
        impsh[f] = (f < (q >> 4)) ? a * 0.125f : -1.0f;
    }
    __syncthreads();
    if (t == 0) {
        for (int it = 0; it < NSEL; it++) {
            float best = -1e30f; int bi = 0;
            for (int f = 0; f < NF; f++)
                if (impsh[f] > best) { best = impsh[f]; bi = f; }
            g_sel[(kv*SQ + q)*NSEL + it] = (best > 0.f) ? bi : -1;
            impsh[bi] = -1e30f;
        }
    }
}

// ---------------- selected + sliding window attention ----------------
__global__ void sel_sw_attn() {
    int q = blockIdx.x, kv = blockIdx.y;
    int t = threadIdx.x;
    __shared__ __align__(16) float qs[4][DH];
    __shared__ float fs[4][80];
    __shared__ float ws[4][65];
    __shared__ int   kp[80];
    __shared__ float red[256];

    for (int i = t; i < 4*DH; i += 256) {
        int g = i >> 7, d = i & 127;
        qs[g][d] = g_rq[(q*HEADS + kv*GG + g)*DH + d];
    }
    if (t < 80) {
        int pos, valid;
        if (t < 64) {
            int blk = g_sel[(kv*SQ + q)*NSEL + (t >> 4)];
            pos = blk*SBS + (t & 15);
            valid = (blk >= 0) && (pos <= q);
        } else {
            pos = (q & ~(SBS-1)) + (t - 64);
            valid = (pos <= q);
        }
        kp[t] = valid ? pos : -1;
    }
    __syncthreads();

    int kbase = (q >= SWIN) ? (q - SWIN) : 0;
    int cnt = q - kbase + 1;

    if (t < 80) {
        int pos = kp[t];
        float a0=-INFINITY,a1=-INFINITY,a2=-INFINITY,a3=-INFINITY;
        if (pos >= 0) {
            const float4* kr = reinterpret_cast<const float4*>(&g_rk[(kv*SQ + pos)*DH]);
            const float4* q0 = reinterpret_cast<const float4*>(qs[0]);
            const float4* q1 = reinterpret_cast<const float4*>(qs[1]);
            const float4* q2 = reinterpret_cast<const float4*>(qs[2]);
            const float4* q3 = reinterpret_cast<const float4*>(qs[3]);
            float s0=0,s1=0,s2=0,s3=0;
            #pragma unroll 8
            for (int d4 = 0; d4 < 32; d4++) {
                float4 b = kr[d4]; float4 a;
                a = q0[d4]; s0 += a.x*b.x + a.y*b.y + a.z*b.z + a.w*b.w;
                a = q1[d4]; s1 += a.x*b.x + a.y*b.y + a.z*b.z + a.w*b.w;
                a = q2[d4]; s2 += a.x*b.x + a.y*b.y + a.z*b.z + a.w*b.w;
                a = q3[d4]; s3 += a.x*b.x + a.y*b.y + a.z*b.z + a.w*b.w;
            }
            a0 = s0*SCALE; a1 = s1*SCALE; a2 = s2*SCALE; a3 = s3*SCALE;
        }
        fs[0][t]=a0; fs[1][t]=a1; fs[2][t]=a2; fs[3][t]=a3;
    }
    if (t >= 128 && t < 193) {
        int j = t - 128;
        float a0=-INFINITY,a1=-INFINITY,a2=-INFINITY,a3=-INFINITY;
        if (j < cnt) {
            int pos = kbase + j;
            const float4* kr = reinterpret_cast<const float4*>(&g_rk[(kv*SQ + pos)*DH]);
            const float4* q0 = reinterpret_cast<const float4*>(qs[0]);
            const float4* q1 = reinterpret_cast<const float4*>(qs[1]);
            const float4* q2 = reinterpret_cast<const float4*>(qs[2]);
            const float4* q3 = reinterpret_cast<const float4*>(qs[3]);
            float s0=0,s1=0,s2=0,s3=0;
            #pragma unroll 8
            for (int d4 = 0; d4 < 32; d4++) {
                float4 b = kr[d4]; float4 a;
                a = q0[d4]; s0 += a.x*b.x + a.y*b.y + a.z*b.z + a.w*b.w;
                a = q1[d4]; s1 += a.x*b.x + a.y*b.y + a.z*b.z + a.w*b.w;
                a = q2[d4]; s2 += a.x*b.x + a.y*b.y + a.z*b.z + a.w*b.w;
                a = q3[d4]; s3 += a.x*b.x + a.y*b.y + a.z*b.z + a.w*b.w;
            }
            a0 = s0*SCALE; a1 = s1*SCALE; a2 = s2*SCALE; a3 = s3*SCALE;
        }
        ws[0][j]=a0; ws[1][j]=a1; ws[2][j]=a2; ws[3][j]=a3;
    }
    __syncthreads();

    for (int g = 0; g < 4; g++) {
        float v = (t < 80) ? fs[g][t] : -INFINITY;
        float m = blkmax(v, red, t);
        float e = (t < 80) ? expf(v - m) : 0.f;
        float s = blksum(e, red, t);
        if (t < 80) fs[g][t] = e / s;
        float v2 = (t < 65) ? ws[g][t] : -INFINITY;
        float m2 = blkmax(v2, red, t);
        float e2 = (t < 65) ? expf(v2 - m2) : 0.f;
        float s2 = blksum(e2, red, t);
        if (t < 65) ws[g][t] = e2 / s2;
        __syncthreads();
    }

    for (int p = t; p < 512; p += 256) {
        int g = p >> 7, d = p & 127;
        float fa = 0.f;
        for (int j = 0; j < 80; j++) {
            int pos = kp[j];
            if (pos >= 0) fa += fs[g][j] * g_qkv[pos*3072 + 2560 + kv*DH + d];
        }
        float wa = 0.f;
        for (int j = 0; j < cnt; j++)
            wa += ws[g][j] * g_qkv[(kbase + j)*3072 + 2560 + kv*DH + d];
        int head = kv*GG + g;
        float g1 = g_comb[q*48 + head*3 + 1];
        float g2 = g_comb[q*48 + head*3 + 2];
        g_att[(q*HEADS + head)*DH + d] += g1*fa + g2*wa;
    }
}

// ---------------- launcher ----------------
extern "C" void kernel_launch(void* const* d_in, const int* in_sizes, int n_in,
                              void* d_out, int out_size) {
    const float* x      = (const float*)d_in[0];
    const float* gnorm  = (const float*)d_in[1];
    const float* w_qkv  = (const float*)d_in[2];
    const float* k_pos  = (const float*)d_in[3];
    const float* v_pos  = (const float*)d_in[4];
    const float* mem_kv = (const float*)d_in[5];
    const float* kc_w1  = (const float*)d_in[6];
    const float* kc_b1  = (const float*)d_in[7];
    const float* kc_w2  = (const float*)d_in[8];
    const float* kc_b2  = (const float*)d_in[9];
    const float* vc_w1  = (const float*)d_in[10];
    const float* vc_b1  = (const float*)d_in[11];
    const float* vc_w2  = (const float*)d_in[12];
    const float* vc_b2  = (const float*)d_in[13];
    const float* w_comb = (const float*)d_in[14];
    const float* b_comb = (const float*)d_in[15];
    const float* w_out  = (const float*)d_in[16];
    float* out = (float*)d_out;

    float *h, *qkv, *comb, *kwf, *vwf, *hid, *craw, *part, *att;
    cudaGetSymbolAddress((void**)&h,    g_h);
    cudaGetSymbolAddress((void**)&qkv,  g_qkv);
    cudaGetSymbolAddress((void**)&comb, g_comb);
    cudaGetSymbolAddress((void**)&kwf,  g_kwflat);
    cudaGetSymbolAddress((void**)&vwf,  g_vwflat);
    cudaGetSymbolAddress((void**)&hid,  g_hidden);
    cudaGetSymbolAddress((void**)&craw, g_craw);
    cudaGetSymbolAddress((void**)&part, g_part);
    cudaGetSymbolAddress((void**)&att,  g_att);

    const int MROWS = KV*NW;   // 1020

    rmsnorm_kernel<<<SQ, 256>>>(x, gnorm);

    // qkv = h @ w_qkv  (2048 x 3072 x 2048)
    bfgemm<<<dim3(3072/128, SQ/128), 256>>>(h, w_qkv, nullptr, qkv, SQ, 3072, DIM, 0, DIM);
    // comb gates = sigmoid(h @ w_comb + b_comb)   (2048 x 48)
    sgemm<<<dim3(1, SQ/64), 256>>>(h, w_comb, b_comb, comb, SQ, 48, DIM, 3);

    // compression MLPs
    build_win<<<dim3(NW, KV), 256>>>(k_pos, v_pos);
    bfgemm<<<dim3(2048/128, 8), 256>>>(kwf, kc_w1, kc_b1, hid, MROWS, 2048, 2048, 2, 2048);
    bfgemm<<<dim3(1, 8, KSPLIT), 256>>>(hid, kc_w2, nullptr, part, MROWS, DH, 2048, 0, 2048/KSPLIT);
    splitk_reduce<<<(MROWS*DH + 255)/256, 256>>>(part, kc_b2, craw, MROWS, DH);
    assemble_c<<<dim3(NKEYS, KV), 128>>>(mem_kv, 0);
    bfgemm<<<dim3(2048/128, 8), 256>>>(vwf, vc_w1, vc_b1, hid, MROWS, 2048, 2048, 2, 2048);
    bfgemm<<<dim3(1, 8, KSPLIT), 256>>>(hid, vc_w2, nullptr, part, MROWS, DH, 2048, 0, 2048/KSPLIT);
    splitk_reduce<<<(MROWS*DH + 255)/256, 256>>>(part, vc_b2, craw, MROWS, DH);
    assemble_c<<<dim3(NKEYS, KV), 128>>>(mem_kv, 1);

    rope_kernel<<<SQ, 256>>>();

    comp_attn<<<dim3(SQ, KV), 256>>>();
    sel_sw_attn<<<dim3(SQ, KV), 256>>>();

    // final projection: att(2048,2048) @ w_out(2048,2048)
    bfgemm<<<dim3(DIM/128, SQ/128), 256>>>(att, w_out, nullptr, out, SQ, DIM, HEADS*DH, 0, HEADS*DH);
}

// round 6
// speedup vs baseline: 3.0400x; 1.4471x over previous
#include <cuda_runtime.h>
#include <cuda_bf16.h>
#include <math.h>
#include <stdint.h>

#define SQ    2048      // sequence length
#define DIM   2048
#define HEADS 16
#define KV    4
#define GG    4         // heads per kv head
#define DH    128
#define NW    255       // num compression windows
#define NKEYS 256       // NMEM + NW
#define NF    128       // num selection blocks
#define NSEL  4
#define SBS   16
#define SWIN  64
#define SCALE 0.08838834764831845f   // 1/sqrt(128)

#define KSPLIT 8        // split-K factor for the small-N MLP layer-2 GEMMs

// ---------------- scratch (device globals; no allocations allowed) -------------
__device__ float g_h[SQ*DIM];
__device__ float g_qkv[SQ*3072];
__device__ float g_comb[SQ*48];
__device__ float g_kwflat[KV*NW*2048];
__device__ float g_vwflat[KV*NW*2048];
__device__ float g_hidden[KV*NW*2048];
__device__ float g_craw[KV*NW*DH];
__device__ float g_part[KSPLIT*KV*NW*DH];      // split-K partials
__device__ float g_ckT[KV*DH*NKEYS];           // ck transposed: [kv][d][key]
__device__ float g_cv[KV*NKEYS*DH];            // [kv][key][d]
__device__ float g_qflat[KV*GG*SQ*DH];         // [kv][g*SQ+s][d]
__device__ float g_sims[KV*GG*SQ*NKEYS];       // [kv][g*SQ+s][key]  (attn in-place)
__device__ float g_coutf[KV*GG*SQ*DH];         // [kv][g*SQ+s][d]
__device__ float g_rq[SQ*HEADS*DH];
__device__ float g_rk[KV*SQ*DH];
__device__ int   g_sel[KV*SQ*NSEL];
__device__ float g_att[SQ*HEADS*DH];

// ---------------- helpers ----------------
// pack two floats into bf16x2 (low half = f0)
__device__ __forceinline__ uint32_t pack_bf16x2(float f0, float f1) {
    uint32_t r;
    asm("cvt.rn.bf16x2.f32 %0, %1, %2;" : "=r"(r) : "f"(f1), "f"(f0));
    return r;
}
// split two floats into hi-bf16x2 and lo-bf16x2
__device__ __forceinline__ void split2(float f0, float f1, uint32_t& hi, uint32_t& lo) {
    hi = pack_bf16x2(f0, f1);
    float h0 = __uint_as_float((hi & 0xFFFFu) << 16);
    float h1 = __uint_as_float(hi & 0xFFFF0000u);
    lo = pack_bf16x2(f0 - h0, f1 - h1);
}

__device__ __forceinline__ void mma_bf16(float* d, const uint32_t* a, const uint32_t* b) {
    asm volatile(
        "mma.sync.aligned.m16n8k16.row.col.f32.bf16.bf16.f32 "
        "{%0,%1,%2,%3}, {%4,%5,%6,%7}, {%8,%9}, {%0,%1,%2,%3};"
        : "+f"(d[0]), "+f"(d[1]), "+f"(d[2]), "+f"(d[3])
        : "r"(a[0]), "r"(a[1]), "r"(a[2]), "r"(a[3]),
          "r"(b[0]), "r"(b[1]));
}

// ---------------- RMSNorm ----------------
__global__ void rmsnorm_kernel(const float* __restrict__ x, const float* __restrict__ g) {
    int s = blockIdx.x;
    int t = threadIdx.x;
    __shared__ float red[256];
    float acc = 0.f;
    for (int i = t; i < DIM; i += 256) { float v = x[s*DIM + i]; acc += v*v; }
    red[t] = acc; __syncthreads();
    for (int st = 128; st > 0; st >>= 1) {
        if (t < st) red[t] += red[t + st];
        __syncthreads();
    }
    float r = rsqrtf(red[0] / (float)DIM + 1e-6f);
    for (int i = t; i < DIM; i += 256) g_h[s*DIM + i] = x[s*DIM + i] * r * g[i];
}

// ---------------- split-BF16 tensor-core GEMM (≈fp32-accurate) ----------------
// A(M,K) row-major fp32, B(K,N) row-major fp32, C(M,N) fp32.
// CTA tile 128x128x32, 256 threads (8 warps), warp tile 32x64.
// Each value split into hi/lo bf16; 3 MMAs: hi*hi + hi*lo + lo*hi (m16n8k16).
// Requires: N % 128 == 0, K % 32 == 0, kslice % 32 == 0. M arbitrary (guarded).
// epi: 0 = none, 1 = +bias, 2 = +bias,relu
// Modes on gridDim.z:
//   bsC != 0 : z = batch index; A/B/C offset by z*bs{A,B,C}; kslice must == K.
//   bsC == 0 && gridDim.z > 1 : split-K; z computes K range [z*kslice,...) and
//     writes a raw partial to C[z*M*N + ...] (epi ignored).
#define A_STR 20     // words per A row (16 data + 4 pad)
#define B_STR 136    // words per B k-pair row (128 data + 8 pad)

__global__ void __launch_bounds__(256) bfgemm(
    const float* __restrict__ A, const float* __restrict__ B,
    const float* __restrict__ bias, float* __restrict__ C,
    int M, int N, int K, int epi, int kslice,
    long bsA, long bsB, long bsC)
{
    __shared__ uint32_t AH[128*A_STR];
    __shared__ uint32_t AL[128*A_STR];
    __shared__ uint32_t BH[16*B_STR];
    __shared__ uint32_t BL[16*B_STR];

    if (bsC != 0) {
        A += (long)blockIdx.z * bsA;
        B += (long)blockIdx.z * bsB;
        C += (long)blockIdx.z * bsC;
    }

    int tid = threadIdx.x;
    int lane = tid & 31;
    int w = tid >> 5;
    int warp_m = w & 3;      // 0..3
    int warp_n = w >> 2;     // 0..1
    int gid = lane >> 2;     // 0..7
    int t4  = lane & 3;      // 0..3

    int row0 = blockIdx.y * 128;
    int col0 = blockIdx.x * 128;
    int kbeg = (bsC != 0) ? 0 : blockIdx.z * kslice;
    int nk = kslice >> 5;

    float acc[2][8][4];
    #pragma unroll
    for (int mf = 0; mf < 2; mf++)
        #pragma unroll
        for (int nf = 0; nf < 8; nf++)
            #pragma unroll
            for (int u = 0; u < 4; u++) acc[mf][nf][u] = 0.f;

    int ar = tid >> 3, af4 = tid & 7;      // A: +32 rows per u
    int bkp = tid >> 5, bc4 = tid & 31;    // B: +8 k-pairs per u

    auto stage = [&](const float4* pa, const float4* pb0, const float4* pb1) {
        #pragma unroll
        for (int u = 0; u < 4; u++) {
            int r = ar + u*32;
            uint32_t h0, l0, h1, l1;
            split2(pa[u].x, pa[u].y, h0, l0);
            split2(pa[u].z, pa[u].w, h1, l1);
            int off = r*A_STR + af4*2;
            *reinterpret_cast<uint2*>(&AH[off]) = make_uint2(h0, h1);
            *reinterpret_cast<uint2*>(&AL[off]) = make_uint2(l0, l1);
        }
        #pragma unroll
        for (int u = 0; u < 2; u++) {
            int kp = bkp + u*8;
            const float* r0 = reinterpret_cast<const float*>(&pb0[u]);
            const float* r1 = reinterpret_cast<const float*>(&pb1[u]);
            uint32_t hh[4], ll[4];
            #pragma unroll
            for (int j = 0; j < 4; j++) split2(r0[j], r1[j], hh[j], ll[j]);
            int off = kp*B_STR + bc4*4;
            *reinterpret_cast<uint4*>(&BH[off]) = make_uint4(hh[0], hh[1], hh[2], hh[3]);
            *reinterpret_cast<uint4*>(&BL[off]) = make_uint4(ll[0], ll[1], ll[2], ll[3]);
        }
    };

    auto loadg = [&](int k0, float4* pa, float4* pb0, float4* pb1) {
        #pragma unroll
        for (int u = 0; u < 4; u++) {
            int gr = row0 + ar + u*32;
            pa[u] = (gr < M) ? *reinterpret_cast<const float4*>(&A[(long)gr*K + k0 + af4*4])
                             : make_float4(0.f,0.f,0.f,0.f);
        }
        #pragma unroll
        for (int u = 0; u < 2; u++) {
            int kk = k0 + (bkp + u*8)*2;
            pb0[u] = *reinterpret_cast<const float4*>(&B[(long)kk*N + col0 + bc4*4]);
            pb1[u] = *reinterpret_cast<const float4*>(&B[(long)(kk+1)*N + col0 + bc4*4]);
        }
    };

    {   // preload tile 0
        float4 pa[4], pb0[2], pb1[2];
        loadg(kbeg, pa, pb0, pb1);
        stage(pa, pb0, pb1);
    }
    __syncthreads();

    int arb = warp_m * 32;
    int cb  = warp_n * 64;

    for (int kt = 0; kt < nk; kt++) {
        float4 pa[4], pb0[2], pb1[2];
        bool nxt = (kt + 1) < nk;
        if (nxt) loadg(kbeg + ((kt + 1) << 5), pa, pb0, pb1);

        #pragma unroll
        for (int s = 0; s < 2; s++) {
            uint32_t ah[2][4], al[2][4];
            #pragma unroll
            for (int mf = 0; mf < 2; mf++) {
                int r = arb + mf*16 + gid;
                int o0 = r*A_STR + s*8 + t4;
                int o1 = (r+8)*A_STR + s*8 + t4;
                ah[mf][0] = AH[o0];   al[mf][0] = AL[o0];
                ah[mf][1] = AH[o1];   al[mf][1] = AL[o1];
                ah[mf][2] = AH[o0+4]; al[mf][2] = AL[o0+4];
                ah[mf][3] = AH[o1+4]; al[mf][3] = AL[o1+4];
            }
            uint32_t bh[8][2], bl[8][2];
            #pragma unroll
            for (int nf = 0; nf < 8; nf++) {
                int c = cb + nf*8 + gid;
                int o0 = (s*8 + t4)*B_STR + c;
                int o1 = o0 + 4*B_STR;
                bh[nf][0] = BH[o0]; bl[nf][0] = BL[o0];
                bh[nf][1] = BH[o1]; bl[nf][1] = BL[o1];
            }
            #pragma unroll
            for (int mf = 0; mf < 2; mf++)
                #pragma unroll
                for (int nf = 0; nf < 8; nf++) {
                    mma_bf16(acc[mf][nf], al[mf], bh[nf]);   // lo*hi
                    mma_bf16(acc[mf][nf], ah[mf], bl[nf]);   // hi*lo
                    mma_bf16(acc[mf][nf], ah[mf], bh[nf]);   // hi*hi
                }
        }

        if (nxt) {
            __syncthreads();
            stage(pa, pb0, pb1);
            __syncthreads();
        }
    }

    // epilogue
    bool partial = (gridDim.z > 1) && (bsC == 0);
    float* Cout = partial ? (C + (long)blockIdx.z * M * N) : C;
    #pragma unroll
    for (int mf = 0; mf < 2; mf++) {
        #pragma unroll
        for (int nf = 0; nf < 8; nf++) {
            int r0 = row0 + arb + mf*16 + gid;
            int c0 = col0 + cb + nf*8 + 2*t4;
            float b0 = 0.f, b1 = 0.f;
            if (!partial && epi >= 1) { b0 = bias[c0]; b1 = bias[c0+1]; }
            if (r0 < M) {
                float v0 = acc[mf][nf][0] + b0;
                float v1 = acc[mf][nf][1] + b1;
                if (!partial && epi == 2) { v0 = fmaxf(v0, 0.f); v1 = fmaxf(v1, 0.f); }
                Cout[(long)r0*N + c0]     = v0;
                Cout[(long)r0*N + c0 + 1] = v1;
            }
            int r1 = r0 + 8;
            if (r1 < M) {
                float v2 = acc[mf][nf][2] + b0;
                float v3 = acc[mf][nf][3] + b1;
                if (!partial && epi == 2) { v2 = fmaxf(v2, 0.f); v3 = fmaxf(v3, 0.f); }
                Cout[(long)r1*N + c0]     = v2;
                Cout[(long)r1*N + c0 + 1] = v3;
            }
        }
    }
}

// reduce split-K partials: out = sum_z part[z] + bias
__global__ void splitk_reduce(const float* __restrict__ part, const float* __restrict__ bias,
                              float* __restrict__ out, int M, int N) {
    int i = blockIdx.x * 256 + threadIdx.x;
    if (i >= M * N) return;
    float a = 0.f;
    #pragma unroll
    for (int z = 0; z < KSPLIT; z++) a += part[(long)z*M*N + i];
    out[i] = a + bias[i % N];
}

// ---------------- small SIMT SGEMM (for comb, N=48) ----------------
__global__ void sgemm(const float* __restrict__ A, const float* __restrict__ B,
                      const float* __restrict__ bias, float* __restrict__ C,
                      int M, int N, int K, int epi)
{
    __shared__ float As[16][64];
    __shared__ float Bs[16][64];
    int tid = threadIdx.x;
    int row0 = blockIdx.y * 64, col0 = blockIdx.x * 64;
    int tr = tid >> 4, tc = tid & 15;
    float acc[4][4] = {};
    for (int k0 = 0; k0 < K; k0 += 16) {
        #pragma unroll
        for (int i = 0; i < 4; i++) {
            int idx = tid + i * 256;
            int r = idx >> 4, c = idx & 15;
            int gr = row0 + r;
            As[c][r] = (gr < M) ? A[gr * K + k0 + c] : 0.f;
            int br = idx >> 6, bc = idx & 63;
            int gc = col0 + bc;
            Bs[br][bc] = (gc < N) ? B[(k0 + br) * N + gc] : 0.f;
        }
        __syncthreads();
        #pragma unroll
        for (int kk = 0; kk < 16; kk++) {
            float a[4], b[4];
            #pragma unroll
            for (int u = 0; u < 4; u++) { a[u] = As[kk][tr*4 + u]; b[u] = Bs[kk][tc*4 + u]; }
            #pragma unroll
            for (int i = 0; i < 4; i++)
                #pragma unroll
                for (int j = 0; j < 4; j++)
                    acc[i][j] = fmaf(a[i], b[j], acc[i][j]);
        }
        __syncthreads();
    }
    #pragma unroll
    for (int i = 0; i < 4; i++) {
        int r = row0 + tr*4 + i;
        if (r >= M) continue;
        #pragma unroll
        for (int j = 0; j < 4; j++) {
            int c = col0 + tc*4 + j;
            if (c >= N) continue;
            float v = acc[i][j];
            if (epi >= 1) {
                v += bias[c];
                if (epi == 2) v = fmaxf(v, 0.f);
                else if (epi == 3) v = 1.f / (1.f + expf(-v));
            }
            C[r * N + c] = v;
        }
    }
}

// ---------------- window gather + positional add ----------------
__global__ void build_win(const float* __restrict__ k_pos, const float* __restrict__ v_pos) {
    int w = blockIdx.x, kh = blockIdx.y;
    int row = kh * NW + w;
    for (int i = threadIdx.x; i < 2048; i += 256) {
        int c = i >> 7, d = i & 127;
        int s = w * 8 + c;
        g_kwflat[row*2048 + i] = g_qkv[s*3072 + 2048 + kh*DH + d] + k_pos[kh*2048 + i];
        g_vwflat[row*2048 + i] = g_qkv[s*3072 + 2560 + kh*DH + d] + v_pos[kh*2048 + i];
    }
}

// ---------------- assemble ckT / cv (prepend memory token) ----------------
__global__ void assemble_cT(const float* __restrict__ mem_kv, int which) {
    int j = blockIdx.x, kh = blockIdx.y;
    int d = threadIdx.x; // 128
    float v;
    if (j == 0) v = mem_kv[which * (KV*DH) + kh*DH + d];
    else        v = g_craw[(kh*NW + (j-1))*DH + d];
    if (which == 0) g_ckT[kh*(DH*NKEYS) + d*NKEYS + j] = v;   // transposed
    else            g_cv[(kh*NKEYS + j)*DH + d] = v;
}

// ---------------- q rearrange for sims GEMM ----------------
__global__ void qflat_copy() {
    int s = blockIdx.x;
    for (int i = threadIdx.x; i < 2048; i += 256) {
        int h = i >> 7, d = i & 127;
        g_qflat[(((h>>2)*GG + (h&3))*SQ + s)*DH + d] = g_qkv[s*3072 + i];
    }
}

// ---------------- RoPE for q (16 heads) and k (4 heads) ----------------
__global__ void rope_kernel() {
    int s = blockIdx.x;
    const float LOG2_10000_OVER_HALF = 0.20762050593046f;  // log2(10000)/64
    for (int p = threadIdx.x; p < 20 * 64; p += 256) {
        int head = p >> 6;
        int i = p & 63;
        float invf = exp2f(-(float)i * LOG2_10000_OVER_HALF);
        float ang = (float)s * invf;
        float sn, cs;
        sincosf(ang, &sn, &cs);
        if (head < HEADS) {
            const float* src = &g_qkv[s*3072 + head*DH];
            float t1 = src[2*i], t2 = src[2*i + 1];
            float* dst = &g_rq[(s*HEADS + head)*DH];
            dst[2*i]     = t1*cs - t2*sn;
            dst[2*i + 1] = t1*sn + t2*cs;
        } else {
            int kh = head - HEADS;
            const float* src = &g_qkv[s*3072 + 2048 + kh*DH];
            float t1 = src[2*i], t2 = src[2*i + 1];
            float* dst = &g_rk[(kh*SQ + s)*DH];
            dst[2*i]     = t1*cs - t2*sn;
            dst[2*i + 1] = t1*sn + t2*cs;
        }
    }
}

// ---------------- masked softmax over sims rows (warp per row) ----------------
__global__ void softmax_rows() {
    int w = threadIdx.x >> 5, lane = threadIdx.x & 31;
    int R = blockIdx.x * 8 + w;          // 0..32767 = kv*8192 + g*2048 + s
    int s = R & (SQ - 1);
    float* row = g_sims + (long)R * NKEYS;
    float v[8];
    float m = -INFINITY;
    #pragma unroll
    for (int k2 = 0; k2 < 8; k2++) {
        int j = k2*32 + lane;
        bool valid = (j == 0) || (s > (j - 1) * 8 + 15);
        v[k2] = valid ? row[j]*SCALE : -INFINITY;
        m = fmaxf(m, v[k2]);
    }
    #pragma unroll
    for (int o = 16; o > 0; o >>= 1) m = fmaxf(m, __shfl_xor_sync(~0u, m, o));
    float sum = 0.f;
    #pragma unroll
    for (int k2 = 0; k2 < 8; k2++) { v[k2] = expf(v[k2] - m); sum += v[k2]; }
    #pragma unroll
    for (int o = 16; o > 0; o >>= 1) sum += __shfl_xor_sync(~0u, sum, o);
    float inv = 1.f / sum;
    #pragma unroll
    for (int k2 = 0; k2 < 8; k2++) row[k2*32 + lane] = v[k2] * inv;
}

// ---------------- importance + top-k selection ----------------
__global__ void topk_kernel() {
    int s = blockIdx.x, kv = blockIdx.y;
    int f = threadIdx.x;   // 0..127
    __shared__ float impsh[NF];
    float a = 0.f;
    #pragma unroll
    for (int g = 0; g < GG; g++) {
        const float* row = g_sims + ((long)(kv*GG + g)*SQ + s) * NKEYS;
        a += row[1 + 2*f];
        if (2*f + 1 < NW) a += row[2 + 2*f];
    }
    impsh[f] = (f < (s >> 4)) ? a * 0.125f : -1.0f;
    __syncthreads();
    if (f == 0) {
        for (int it = 0; it < NSEL; it++) {
            float best = -1e30f; int bi = 0;
            for (int j = 0; j < NF; j++)
                if (impsh[j] > best) { best = impsh[j]; bi = j; }
            g_sel[(kv*SQ + s)*NSEL + it] = (best > 0.f) ? bi : -1;
            impsh[bi] = -1e30f;
        }
    }
}

// ---------------- combine: g_att = gate0 * cout ----------------
__global__ void combine_c() {
    int s = blockIdx.x;
    for (int i = threadIdx.x; i < 2048; i += 256) {
        int h = i >> 7, d = i & 127;
        int kv = h >> 2, g = h & 3;
        float c = g_coutf[((long)(kv*GG + g)*SQ + s)*DH + d];
        g_att[(s*HEADS + h)*DH + d] = g_comb[s*48 + h*3] * c;
    }
}

// ---------------- selected + sliding window attention (warp per head) --------
__global__ void __launch_bounds__(128) sel_sw2() {
    int q = blockIdx.x, kv = blockIdx.y;
    int t = threadIdx.x, lane = t & 31, g = t >> 5;
    __shared__ int   kp[80];
    __shared__ float fat[4][80];
    __shared__ float wat[4][72];

    if (t < 80) {
        int pos, valid;
        if (t < 64) {
            int blk = g_sel[(kv*SQ + q)*NSEL + (t >> 4)];
            pos = blk*SBS + (t & 15);
            valid = (blk >= 0) && (pos <= q);
        } else {
            pos = (q & ~(SBS-1)) + (t - 64);
            valid = (pos <= q);
        }
        kp[t] = valid ? pos : -1;
    }
    __syncthreads();

    float4 qv = *reinterpret_cast<const float4*>(&g_rq[((long)q*HEADS + kv*GG + g)*DH + lane*4]);
    int kbase = (q >= SWIN) ? (q - SWIN) : 0;
    int cnt = q - kbase + 1;   // <= 65

    // selected sims (80 keys, batches of 8)
    #pragma unroll 1
    for (int b = 0; b < 10; b++) {
        float part[8];
        #pragma unroll
        for (int jj = 0; jj < 8; jj++) {
            int pos = kp[b*8 + jj];
            float p = 0.f;
            if (pos >= 0) {
                float4 kk = *reinterpret_cast<const float4*>(&g_rk[((long)kv*SQ + pos)*DH + lane*4]);
                p = qv.x*kk.x + qv.y*kk.y + qv.z*kk.z + qv.w*kk.w;
            }
            part[jj] = p;
        }
        #pragma unroll
        for (int o = 16; o > 0; o >>= 1)
            #pragma unroll
            for (int jj = 0; jj < 8; jj++) part[jj] += __shfl_xor_sync(~0u, part[jj], o);
        if (lane < 8) {
            int j = b*8 + lane;
            fat[g][j] = (kp[j] >= 0) ? part[lane]*SCALE : -INFINITY;
        }
    }
    // sliding sims (72 slots, valid j < cnt)
    #pragma unroll 1
    for (int b = 0; b < 9; b++) {
        float part[8];
        #pragma unroll
        for (int jj = 0; jj < 8; jj++) {
            int j = b*8 + jj;
            float p = 0.f;
            if (j < cnt) {
                float4 kk = *reinterpret_cast<const float4*>(&g_rk[((long)kv*SQ + kbase + j)*DH + lane*4]);
                p = qv.x*kk.x + qv.y*kk.y + qv.z*kk.z + qv.w*kk.w;
            }
            part[jj] = p;
        }
        #pragma unroll
        for (int o = 16; o > 0; o >>= 1)
            #pragma unroll
            for (int jj = 0; jj < 8; jj++) part[jj] += __shfl_xor_sync(~0u, part[jj], o);
        if (lane < 8) {
            int j = b*8 + lane;
            wat[g][j] = (j < cnt) ? part[lane]*SCALE : -INFINITY;
        }
    }
    __syncwarp();

    // softmax selected (80 entries)
    {
        float v0 = fat[g][lane];
        float v1 = fat[g][lane + 32];
        float v2 = (lane < 16) ? fat[g][lane + 64] : -INFINITY;
        float m = fmaxf(v0, fmaxf(v1, v2));
        #pragma unroll
        for (int o = 16; o > 0; o >>= 1) m = fmaxf(m, __shfl_xor_sync(~0u, m, o));
        float e0 = expf(v0 - m), e1 = expf(v1 - m), e2 = (lane < 16) ? expf(v2 - m) : 0.f;
        float sum = e0 + e1 + e2;
        #pragma unroll
        for (int o = 16; o > 0; o >>= 1) sum += __shfl_xor_sync(~0u, sum, o);
        float inv = 1.f / sum;
        fat[g][lane] = e0 * inv;
        fat[g][lane + 32] = e1 * inv;
        if (lane < 16) fat[g][lane + 64] = e2 * inv;
    }
    // softmax sliding (65 valid of 72)
    {
        float v0 = wat[g][lane];
        float v1 = wat[g][lane + 32];
        float v2 = (lane < 8) ? wat[g][lane + 64] : -INFINITY;
        float m = fmaxf(v0, fmaxf(v1, v2));
        #pragma unroll
        for (int o = 16; o > 0; o >>= 1) m = fmaxf(m, __shfl_xor_sync(~0u, m, o));
        float e0 = expf(v0 - m), e1 = expf(v1 - m), e2 = (lane < 8) ? expf(v2 - m) : 0.f;
        float sum = e0 + e1 + e2;
        #pragma unroll
        for (int o = 16; o > 0; o >>= 1) sum += __shfl_xor_sync(~0u, sum, o);
        float inv = 1.f / sum;
        wat[g][lane] = e0 * inv;
        wat[g][lane + 32] = e1 * inv;
        if (lane < 8) wat[g][lane + 64] = e2 * inv;
    }
    __syncwarp();

    // PV
    float4 fa = make_float4(0.f,0.f,0.f,0.f);
    float4 wa = make_float4(0.f,0.f,0.f,0.f);
    #pragma unroll 4
    for (int j = 0; j < 80; j++) {
        int pos = kp[j];
        if (pos >= 0) {
            float a = fat[g][j];
            float4 vv = *reinterpret_cast<const float4*>(&g_qkv[(long)pos*3072 + 2560 + kv*DH + lane*4]);
            fa.x += a*vv.x; fa.y += a*vv.y; fa.z += a*vv.z; fa.w += a*vv.w;
        }
    }
    #pragma unroll 4
    for (int j = 0; j < 65; j++) {
        if (j < cnt) {
            float a = wat[g][j];
            float4 vv = *reinterpret_cast<const float4*>(&g_qkv[(long)(kbase + j)*3072 + 2560 + kv*DH + lane*4]);
            wa.x += a*vv.x; wa.y += a*vv.y; wa.z += a*vv.z; wa.w += a*vv.w;
        }
    }

    int head = kv*GG + g;
    float g1 = g_comb[q*48 + head*3 + 1];
    float g2 = g_comb[q*48 + head*3 + 2];
    float* o = &g_att[((long)q*HEADS + head)*DH + lane*4];
    float4 cur = *reinterpret_cast<float4*>(o);
    cur.x += g1*fa.x + g2*wa.x;
    cur.y += g1*fa.y + g2*wa.y;
    cur.z += g1*fa.z + g2*wa.z;
    cur.w += g1*fa.w + g2*wa.w;
    *reinterpret_cast<float4*>(o) = cur;
}

// ---------------- launcher ----------------
extern "C" void kernel_launch(void* const* d_in, const int* in_sizes, int n_in,
                              void* d_out, int out_size) {
    const float* x      = (const float*)d_in[0];
    const float* gnorm  = (const float*)d_in[1];
    const float* w_qkv  = (const float*)d_in[2];
    const float* k_pos  = (const float*)d_in[3];
    const float* v_pos  = (const float*)d_in[4];
    const float* mem_kv = (const float*)d_in[5];
    const float* kc_w1  = (const float*)d_in[6];
    const float* kc_b1  = (const float*)d_in[7];
    const float* kc_w2  = (const float*)d_in[8];
    const float* kc_b2  = (const float*)d_in[9];
    const float* vc_w1  = (const float*)d_in[10];
    const float* vc_b1  = (const float*)d_in[11];
    const float* vc_w2  = (const float*)d_in[12];
    const float* vc_b2  = (const float*)d_in[13];
    const float* w_comb = (const float*)d_in[14];
    const float* b_comb = (const float*)d_in[15];
    const float* w_out  = (const float*)d_in[16];
    float* out = (float*)d_out;

    float *h, *qkv, *comb, *kwf, *vwf, *hid, *craw, *part, *att;
    float *ckT, *cv, *qflat, *sims, *coutf;
    cudaGetSymbolAddress((void**)&h,     g_h);
    cudaGetSymbolAddress((void**)&qkv,   g_qkv);
    cudaGetSymbolAddress((void**)&comb,  g_comb);
    cudaGetSymbolAddress((void**)&kwf,   g_kwflat);
    cudaGetSymbolAddress((void**)&vwf,   g_vwflat);
    cudaGetSymbolAddress((void**)&hid,   g_hidden);
    cudaGetSymbolAddress((void**)&craw,  g_craw);
    cudaGetSymbolAddress((void**)&part,  g_part);
    cudaGetSymbolAddress((void**)&att,   g_att);
    cudaGetSymbolAddress((void**)&ckT,   g_ckT);
    cudaGetSymbolAddress((void**)&cv,    g_cv);
    cudaGetSymbolAddress((void**)&qflat, g_qflat);
    cudaGetSymbolAddress((void**)&sims,  g_sims);
    cudaGetSymbolAddress((void**)&coutf, g_coutf);

    const int MROWS = KV*NW;   // 1020
    const int MQ = KV*GG*SQ/KV;  // 8192 rows per kv batch

    rmsnorm_kernel<<<SQ, 256>>>(x, gnorm);

    // qkv = h @ w_qkv  (2048 x 3072 x 2048)
    bfgemm<<<dim3(3072/128, SQ/128), 256>>>(h, w_qkv, nullptr, qkv, SQ, 3072, DIM, 0, DIM, 0, 0, 0);
    // comb gates = sigmoid(h @ w_comb + b_comb)   (2048 x 48)
    sgemm<<<dim3(1, SQ/64), 256>>>(h, w_comb, b_comb, comb, SQ, 48, DIM, 3);

    qflat_copy<<<SQ, 256>>>();

    // compression MLPs
    build_win<<<dim3(NW, KV), 256>>>(k_pos, v_pos);
    bfgemm<<<dim3(2048/128, 8), 256>>>(kwf, kc_w1, kc_b1, hid, MROWS, 2048, 2048, 2, 2048, 0, 0, 0);
    bfgemm<<<dim3(1, 8, KSPLIT), 256>>>(hid, kc_w2, nullptr, part, MROWS, DH, 2048, 0, 2048/KSPLIT, 0, 0, 0);
    splitk_reduce<<<(MROWS*DH + 255)/256, 256>>>(part, kc_b2, craw, MROWS, DH);
    assemble_cT<<<dim3(NKEYS, KV), 128>>>(mem_kv, 0);
    bfgemm<<<dim3(2048/128, 8), 256>>>(vwf, vc_w1, vc_b1, hid, MROWS, 2048, 2048, 2, 2048, 0, 0, 0);
    bfgemm<<<dim3(1, 8, KSPLIT), 256>>>(hid, vc_w2, nullptr, part, MROWS, DH, 2048, 0, 2048/KSPLIT, 0, 0, 0);
    splitk_reduce<<<(MROWS*DH + 255)/256, 256>>>(part, vc_b2, craw, MROWS, DH);
    assemble_cT<<<dim3(NKEYS, KV), 128>>>(mem_kv, 1);

    rope_kernel<<<SQ, 256>>>();

    // compressed attention as batched GEMMs
    // sims[kv] = qflat[kv] (8192x128) @ ckT[kv] (128x256)
    bfgemm<<<dim3(NKEYS/128, MQ/128, KV), 256>>>(qflat, ckT, nullptr, sims,
        MQ, NKEYS, DH, 0, DH, (long)MQ*DH, (long)DH*NKEYS, (long)MQ*NKEYS);
    softmax_rows<<<KV*GG*SQ/8, 256>>>();
    topk_kernel<<<dim3(SQ, KV), 128>>>();
    // cout[kv] = attn[kv] (8192x256) @ cv[kv] (256x128)
    bfgemm<<<dim3(DH/128, MQ/128, KV), 256>>>(sims, cv, nullptr, coutf,
        MQ, DH, NKEYS, 0, NKEYS, (long)MQ*NKEYS, (long)NKEYS*DH, (long)MQ*DH);
    combine_c<<<SQ, 256>>>();

    sel_sw2<<<dim3(SQ, KV), 128>>>();

    // final projection: att(2048,2048) @ w_out(2048,2048)
    bfgemm<<<dim3(DIM/128, SQ/128), 256>>>(att, w_out, nullptr, out, SQ, DIM, HEADS*DH, 0, HEADS*DH, 0, 0, 0);
}